// round 1
// baseline (speedup 1.0000x reference)
#include <cuda_runtime.h>
#include <math_constants.h>

#define BB 4
#define TT 2048
#define DD 1024

// Scratch (allocation-free rule: __device__ globals)
__device__ float g_Q[(size_t)BB * TT * DD];
__device__ float g_K[(size_t)BB * TT * DD];
__device__ float g_V[(size_t)BB * TT * DD];
__device__ float g_S[(size_t)BB * TT * TT];

// ---------------------------------------------------------------------------
// Tiled fp32 GEMM body: C[m,n] = scale * sum_k A[m,k] * B'[k,n]
//   BT = true : B is stored [N][K] row-major (we multiply by B^T)   -> "NT"
//   BT = false: B is stored [K][N] row-major                        -> "NN"
// Tile: 128x128 output per block, K-step 8, 256 threads, 8x8 per thread.
// Requires M,N % 128 == 0 and K % 8 == 0 (true for all shapes here).
// ---------------------------------------------------------------------------
template <bool BT>
__device__ __forceinline__ void gemm_body(const float* __restrict__ A,
                                          const float* __restrict__ Bm,
                                          float* __restrict__ C,
                                          int N, int K, float scale)
{
    __shared__ float As[8][132];
    __shared__ float Bs[8][132];

    const int tid = threadIdx.x;
    const int tx  = tid & 15;        // 16 thread-cols
    const int ty  = tid >> 4;        // 16 thread-rows
    const int m0  = blockIdx.y * 128;
    const int n0  = blockIdx.x * 128;

    float acc[8][8];
#pragma unroll
    for (int i = 0; i < 8; i++)
#pragma unroll
        for (int j = 0; j < 8; j++) acc[i][j] = 0.f;

    for (int k0 = 0; k0 < K; k0 += 8) {
        // Load A tile (128 rows x 8 k), transpose into As[k][m]
        {
            const int r  = tid >> 1;
            const int kq = (tid & 1) * 4;
            float4 v = *(const float4*)(A + (size_t)(m0 + r) * K + k0 + kq);
            As[kq + 0][r] = v.x; As[kq + 1][r] = v.y;
            As[kq + 2][r] = v.z; As[kq + 3][r] = v.w;
        }
        if (BT) {
            // B stored [N][K]: load 128 n-rows x 8 k, transpose into Bs[k][n]
            const int r  = tid >> 1;
            const int kq = (tid & 1) * 4;
            float4 v = *(const float4*)(Bm + (size_t)(n0 + r) * K + k0 + kq);
            Bs[kq + 0][r] = v.x; Bs[kq + 1][r] = v.y;
            Bs[kq + 2][r] = v.z; Bs[kq + 3][r] = v.w;
        } else {
            // B stored [K][N]: load 8 k-rows x 128 n directly into Bs[k][n]
            const int kr = tid >> 5;
            const int nc = (tid & 31) * 4;
            float4 v = *(const float4*)(Bm + (size_t)(k0 + kr) * N + n0 + nc);
            *(float4*)&Bs[kr][nc] = v;
        }
        __syncthreads();

#pragma unroll
        for (int kk = 0; kk < 8; kk++) {
            float ra[8], rb[8];
            *(float4*)(ra)     = *(const float4*)&As[kk][ty * 8];
            *(float4*)(ra + 4) = *(const float4*)&As[kk][ty * 8 + 4];
            *(float4*)(rb)     = *(const float4*)&Bs[kk][tx * 8];
            *(float4*)(rb + 4) = *(const float4*)&Bs[kk][tx * 8 + 4];
#pragma unroll
            for (int i = 0; i < 8; i++)
#pragma unroll
                for (int j = 0; j < 8; j++)
                    acc[i][j] = fmaf(ra[i], rb[j], acc[i][j]);
        }
        __syncthreads();
    }

#pragma unroll
    for (int i = 0; i < 8; i++) {
        const size_t row = (size_t)(m0 + ty * 8 + i);
        float4 o0, o1;
        o0.x = acc[i][0] * scale; o0.y = acc[i][1] * scale;
        o0.z = acc[i][2] * scale; o0.w = acc[i][3] * scale;
        o1.x = acc[i][4] * scale; o1.y = acc[i][5] * scale;
        o1.z = acc[i][6] * scale; o1.w = acc[i][7] * scale;
        *(float4*)(C + row * N + n0 + tx * 8)     = o0;
        *(float4*)(C + row * N + n0 + tx * 8 + 4) = o1;
    }
}

// QKV projection: [8192,1024] = x[8192,1024] @ W[1024,1024]^T
__global__ __launch_bounds__(256) void qkv_kernel(const float* __restrict__ x,
                                                  const float* __restrict__ W,
                                                  int which)
{
    float* C = (which == 0) ? g_Q : (which == 1) ? g_K : g_V;
    gemm_body<true>(x, W, C, DD, DD, 1.0f);
}

// Scores: S[b] = Q[b] @ K[b]^T / sqrt(D)
__global__ __launch_bounds__(256) void scores_kernel()
{
    const int b = blockIdx.z;
    gemm_body<true>(g_Q + (size_t)b * TT * DD,
                    g_K + (size_t)b * TT * DD,
                    g_S + (size_t)b * TT * TT,
                    TT, DD, 0.03125f /* 1/sqrt(1024) */);
}

// Row softmax over g_S (8192 rows of 2048); row lives in registers.
__global__ __launch_bounds__(256) void softmax_kernel()
{
    const size_t row = blockIdx.x;
    float* r = g_S + row * TT;
    const int t = threadIdx.x;

    float v[8];
#pragma unroll
    for (int i = 0; i < 8; i++) v[i] = r[t + i * 256];

    float m = -CUDART_INF_F;
#pragma unroll
    for (int i = 0; i < 8; i++) m = fmaxf(m, v[i]);

    __shared__ float red[256];
    red[t] = m;
    __syncthreads();
    for (int s = 128; s > 0; s >>= 1) {
        if (t < s) red[t] = fmaxf(red[t], red[t + s]);
        __syncthreads();
    }
    m = red[0];
    __syncthreads();

    float sum = 0.f;
#pragma unroll
    for (int i = 0; i < 8; i++) { v[i] = __expf(v[i] - m); sum += v[i]; }
    red[t] = sum;
    __syncthreads();
    for (int s = 128; s > 0; s >>= 1) {
        if (t < s) red[t] += red[t + s];
        __syncthreads();
    }
    const float inv = 1.0f / red[0];
#pragma unroll
    for (int i = 0; i < 8; i++) r[t + i * 256] = v[i] * inv;
}

// Output: out[b] = softmax(S[b]) @ V[b]   (NN gemm, K = 2048)
__global__ __launch_bounds__(256) void out_kernel(float* __restrict__ out)
{
    const int b = blockIdx.z;
    gemm_body<false>(g_S + (size_t)b * TT * TT,
                     g_V + (size_t)b * TT * DD,
                     out + (size_t)b * TT * DD,
                     DD, TT, 1.0f);
}

extern "C" void kernel_launch(void* const* d_in, const int* in_sizes, int n_in,
                              void* d_out, int out_size)
{
    (void)in_sizes; (void)n_in; (void)out_size;
    const float* x  = (const float*)d_in[0];
    const float* Wq = (const float*)d_in[1];
    const float* Wk = (const float*)d_in[2];
    const float* Wv = (const float*)d_in[3];
    float* out = (float*)d_out;

    dim3 gQKV(DD / 128, (BB * TT) / 128);      // (8, 64)
    qkv_kernel<<<gQKV, 256>>>(x, Wq, 0);
    qkv_kernel<<<gQKV, 256>>>(x, Wk, 1);
    qkv_kernel<<<gQKV, 256>>>(x, Wv, 2);

    dim3 gS(TT / 128, TT / 128, BB);           // (16, 16, 4)
    scores_kernel<<<gS, 256>>>();

    softmax_kernel<<<BB * TT, 256>>>();

    dim3 gO(DD / 128, TT / 128, BB);           // (8, 16, 4)
    out_kernel<<<gO, 256>>>(out);
}

// round 3
// speedup vs baseline: 3.0297x; 3.0297x over previous
#include <cuda_runtime.h>
#include <cuda_bf16.h>
#include <stdint.h>
#include <math_constants.h>

#define BB 4
#define TT 2048
#define DD 1024
#define KCH 32

// Scratch (allocation-free rule: __device__ globals), all fp32
__device__ float g_Q[(size_t)BB * TT * DD];
__device__ float g_K[(size_t)BB * TT * DD];
__device__ float g_V[(size_t)BB * TT * DD];
__device__ float g_S[(size_t)BB * TT * TT];

// Dynamic SMEM: 2 stages x (A_hi 8K | A_lo 8K | B_hi 8K | B_lo 8K) = 64 KB
#define STAGE_BYTES 32768
#define SMEM_BYTES  (2 * STAGE_BYTES)

__device__ __forceinline__ uint32_t smem_u32(const void* p) {
    uint32_t a;
    asm("{ .reg .u64 t; cvta.to.shared.u64 t, %1; cvt.u32.u64 %0, t; }" : "=r"(a) : "l"(p));
    return a;
}
// SW64 swizzle: 8 rows x 64B atom, conflict-free for 16B ldmatrix rows
__device__ __forceinline__ uint32_t sw64(uint32_t o) { return o ^ ((o >> 3) & 0x30); }

__device__ __forceinline__ void ldsm4(uint32_t addr, uint32_t r[4]) {
    asm volatile("ldmatrix.sync.aligned.m8n8.x4.shared.b16 {%0,%1,%2,%3}, [%4];"
                 : "=r"(r[0]), "=r"(r[1]), "=r"(r[2]), "=r"(r[3]) : "r"(addr));
}
__device__ __forceinline__ void mma16816(float c[4], const uint32_t a[4],
                                         uint32_t b0, uint32_t b1) {
    asm volatile("mma.sync.aligned.m16n8k16.row.col.f32.bf16.bf16.f32 "
                 "{%0,%1,%2,%3}, {%4,%5,%6,%7}, {%8,%9}, {%0,%1,%2,%3};"
                 : "+f"(c[0]), "+f"(c[1]), "+f"(c[2]), "+f"(c[3])
                 : "r"(a[0]), "r"(a[1]), "r"(a[2]), "r"(a[3]), "r"(b0), "r"(b1));
}

// fp32 pair -> (hi bf16x2 word, lo bf16x2 word), lo = RN(v - float(hi))
__device__ __forceinline__ void split2(float a, float b, uint32_t& hi, uint32_t& lo) {
    __nv_bfloat162 h = __floats2bfloat162_rn(a, b);
    float ra = a - __bfloat162float(h.x);
    float rb = b - __bfloat162float(h.y);
    __nv_bfloat162 l = __floats2bfloat162_rn(ra, rb);
    hi = *reinterpret_cast<uint32_t*>(&h);
    lo = *reinterpret_cast<uint32_t*>(&l);
}

// ---------------------------------------------------------------------------
// HMMA split-bf16 GEMM: C[m,n] = scale * sum_k A[m,k] * B'[k,n]
//   BT=true : B stored [N][K] row-major (NT);  BT=false: B stored [K][N] (NN)
// 128x128 CTA tile, 8 warps (2Mx4N -> 64x32 warp tile), K-chunk 32,
// double-buffered SMEM, split-bf16 3-pass accumulation in fp32 registers.
// ---------------------------------------------------------------------------
template <bool BT>
__device__ __forceinline__ void gemm_mma(const float* __restrict__ A,
                                         const float* __restrict__ Bm,
                                         float* __restrict__ C,
                                         int Ntot, int K, float scale)
{
    extern __shared__ char smc[];
    const uint32_t sb  = smem_u32(smc);
    const int tid  = threadIdx.x;
    const int lane = tid & 31;
    const int wid  = tid >> 5;
    const int wr   = wid >> 2;          // warp row (0..1) -> m offset wr*64
    const int wc   = wid & 3;           // warp col (0..3) -> n offset wc*32
    const int m0   = blockIdx.y * 128;
    const int n0   = blockIdx.x * 128;

    float acc[4][4][4];
#pragma unroll
    for (int i = 0; i < 4; i++)
#pragma unroll
        for (int j = 0; j < 4; j++)
#pragma unroll
            for (int e = 0; e < 4; e++) acc[i][j][e] = 0.f;

    const int nch = K / KCH;

    // ---- stage chunk c into buffer buf ----
    auto stage = [&](int c, int buf) {
        char* aHi = smc + buf * STAGE_BYTES;
        char* aLo = aHi + 8192;
        char* bHi = aHi + 16384;
        char* bLo = aHi + 24576;
        const int k0 = c * KCH;
#pragma unroll
        for (int i = 0; i < 4; i++) {           // A: 128 rows x 32 k
            int u = tid + i * 256;
            int row = u >> 3, kq = (u & 7) * 4;
            float4 v = *(const float4*)(A + (size_t)(m0 + row) * K + k0 + kq);
            uint32_t h0, l0, h1, l1;
            split2(v.x, v.y, h0, l0);
            split2(v.z, v.w, h1, l1);
            uint32_t off = sw64((uint32_t)(row * 64 + kq * 2));
            *(uint2*)(aHi + off) = make_uint2(h0, h1);
            *(uint2*)(aLo + off) = make_uint2(l0, l1);
        }
        if (BT) {
#pragma unroll
            for (int i = 0; i < 4; i++) {       // B: 128 n-rows x 32 k
                int u = tid + i * 256;
                int row = u >> 3, kq = (u & 7) * 4;
                float4 v = *(const float4*)(Bm + (size_t)(n0 + row) * K + k0 + kq);
                uint32_t h0, l0, h1, l1;
                split2(v.x, v.y, h0, l0);
                split2(v.z, v.w, h1, l1);
                uint32_t off = sw64((uint32_t)(row * 64 + kq * 2));
                *(uint2*)(bHi + off) = make_uint2(h0, h1);
                *(uint2*)(bLo + off) = make_uint2(l0, l1);
            }
        } else {
#pragma unroll
            for (int i = 0; i < 4; i++) {       // B [K][N]: gather into [n][k]
                int u = tid + i * 256;
                int n = u & 127, kq = (u >> 7) * 4;
                const float* bp = Bm + (size_t)(k0 + kq) * Ntot + n0 + n;
                float x0 = bp[0];
                float x1 = bp[(size_t)Ntot];
                float x2 = bp[2 * (size_t)Ntot];
                float x3 = bp[3 * (size_t)Ntot];
                uint32_t h0, l0, h1, l1;
                split2(x0, x1, h0, l0);
                split2(x2, x3, h1, l1);
                uint32_t off = sw64((uint32_t)(n * 64 + kq * 2));
                *(uint2*)(bHi + off) = make_uint2(h0, h1);
                *(uint2*)(bLo + off) = make_uint2(l0, l1);
            }
        }
    };

    // ---- compute one staged chunk ----
    auto compute = [&](int buf) {
        const uint32_t base = sb + buf * STAGE_BYTES;
#pragma unroll
        for (int ks = 0; ks < KCH / 16; ks++) {
            // per-thread ldmatrix addresses
            const uint32_t aoff =
                sw64((uint32_t)((wr * 64 + (lane & 15)) * 64 +
                                (ks * 2 + (lane >> 4)) * 16));
            const uint32_t boff =
                sw64((uint32_t)((wc * 32 + ((lane >> 3) >> 1) * 8 + (lane & 7)) * 64 +
                                (ks * 2 + ((lane >> 3) & 1)) * 16));
            // ng=1 adds 16 rows -> +1024 bytes (swizzle-invariant)
            uint32_t Ah[4][4], Bh[2][4], Bl[2][4];
#pragma unroll
            for (int mt = 0; mt < 4; mt++)
                ldsm4(base + aoff + mt * 1024, Ah[mt]);                  // A_hi
#pragma unroll
            for (int ng = 0; ng < 2; ng++) {
                ldsm4(base + 16384 + boff + ng * 1024, Bh[ng]);          // B_hi
                ldsm4(base + 24576 + boff + ng * 1024, Bl[ng]);          // B_lo
            }
            // pass 1: hi*hi
#pragma unroll
            for (int mt = 0; mt < 4; mt++)
#pragma unroll
                for (int ng = 0; ng < 2; ng++) {
                    mma16816(acc[mt][ng * 2],     Ah[mt], Bh[ng][0], Bh[ng][1]);
                    mma16816(acc[mt][ng * 2 + 1], Ah[mt], Bh[ng][2], Bh[ng][3]);
                }
            // pass 2: hi*lo
#pragma unroll
            for (int mt = 0; mt < 4; mt++)
#pragma unroll
                for (int ng = 0; ng < 2; ng++) {
                    mma16816(acc[mt][ng * 2],     Ah[mt], Bl[ng][0], Bl[ng][1]);
                    mma16816(acc[mt][ng * 2 + 1], Ah[mt], Bl[ng][2], Bl[ng][3]);
                }
            // pass 3: lo*hi (load A_lo late to cap register pressure)
            uint32_t Al[4][4];
#pragma unroll
            for (int mt = 0; mt < 4; mt++)
                ldsm4(base + 8192 + aoff + mt * 1024, Al[mt]);
#pragma unroll
            for (int mt = 0; mt < 4; mt++)
#pragma unroll
                for (int ng = 0; ng < 2; ng++) {
                    mma16816(acc[mt][ng * 2],     Al[mt], Bh[ng][0], Bh[ng][1]);
                    mma16816(acc[mt][ng * 2 + 1], Al[mt], Bh[ng][2], Bh[ng][3]);
                }
        }
    };

    stage(0, 0);
    __syncthreads();
    for (int c = 0; c < nch; c++) {
        if (c + 1 < nch) stage(c + 1, (c + 1) & 1);   // overlap loads with MMA
        compute(c & 1);
        __syncthreads();
    }

    // ---- epilogue ----
#pragma unroll
    for (int mt = 0; mt < 4; mt++)
#pragma unroll
        for (int nt = 0; nt < 4; nt++) {
            const float* a4 = acc[mt][nt];
            const int r   = m0 + wr * 64 + mt * 16 + (lane >> 2);
            const int col = n0 + wc * 32 + nt * 8 + (lane & 3) * 2;
            float2 v0 = make_float2(a4[0] * scale, a4[1] * scale);
            float2 v1 = make_float2(a4[2] * scale, a4[3] * scale);
            *(float2*)(C + (size_t)r * Ntot + col)       = v0;
            *(float2*)(C + (size_t)(r + 8) * Ntot + col) = v1;
        }
}

// ---------------------------------------------------------------------------
__global__ __launch_bounds__(256, 2) void qkv_kernel(const float* __restrict__ x,
                                                     const float* __restrict__ Wq,
                                                     const float* __restrict__ Wk,
                                                     const float* __restrict__ Wv)
{
    const int which = blockIdx.z;
    const float* W = (which == 0) ? Wq : (which == 1) ? Wk : Wv;
    float* C = (which == 0) ? g_Q : (which == 1) ? g_K : g_V;
    gemm_mma<true>(x, W, C, DD, DD, 1.0f);
}

__global__ __launch_bounds__(256, 2) void scores_kernel()
{
    const int b = blockIdx.z;
    gemm_mma<true>(g_Q + (size_t)b * TT * DD,
                   g_K + (size_t)b * TT * DD,
                   g_S + (size_t)b * TT * TT,
                   TT, DD, 0.03125f /* 1/sqrt(1024) */);
}

__global__ __launch_bounds__(256, 2) void out_kernel(float* __restrict__ out)
{
    const int b = blockIdx.z;
    gemm_mma<false>(g_S + (size_t)b * TT * TT,
                    g_V + (size_t)b * TT * DD,
                    out + (size_t)b * TT * DD,
                    DD, TT, 1.0f);
}

// Row softmax over g_S (8192 rows of 2048); row lives in registers.
__global__ __launch_bounds__(256) void softmax_kernel()
{
    const size_t row = blockIdx.x;
    float* r = g_S + row * TT;
    const int t = threadIdx.x;

    float v[8];
#pragma unroll
    for (int i = 0; i < 8; i++) v[i] = r[t + i * 256];

    float m = -CUDART_INF_F;
#pragma unroll
    for (int i = 0; i < 8; i++) m = fmaxf(m, v[i]);

    __shared__ float red[256];
    red[t] = m;
    __syncthreads();
    for (int s = 128; s > 0; s >>= 1) {
        if (t < s) red[t] = fmaxf(red[t], red[t + s]);
        __syncthreads();
    }
    m = red[0];
    __syncthreads();

    float sum = 0.f;
#pragma unroll
    for (int i = 0; i < 8; i++) { v[i] = __expf(v[i] - m); sum += v[i]; }
    red[t] = sum;
    __syncthreads();
    for (int s = 128; s > 0; s >>= 1) {
        if (t < s) red[t] += red[t + s];
        __syncthreads();
    }
    const float inv = 1.0f / red[0];
#pragma unroll
    for (int i = 0; i < 8; i++) r[t + i * 256] = v[i] * inv;
}

extern "C" void kernel_launch(void* const* d_in, const int* in_sizes, int n_in,
                              void* d_out, int out_size)
{
    (void)in_sizes; (void)n_in; (void)out_size;
    const float* x  = (const float*)d_in[0];
    const float* Wq = (const float*)d_in[1];
    const float* Wk = (const float*)d_in[2];
    const float* Wv = (const float*)d_in[3];
    float* out = (float*)d_out;

    cudaFuncSetAttribute(qkv_kernel,    cudaFuncAttributeMaxDynamicSharedMemorySize, SMEM_BYTES);
    cudaFuncSetAttribute(scores_kernel, cudaFuncAttributeMaxDynamicSharedMemorySize, SMEM_BYTES);
    cudaFuncSetAttribute(out_kernel,    cudaFuncAttributeMaxDynamicSharedMemorySize, SMEM_BYTES);

    dim3 gQKV(DD / 128, (BB * TT) / 128, 3);     // (8, 64, 3)
    qkv_kernel<<<gQKV, 256, SMEM_BYTES>>>(x, Wq, Wk, Wv);

    dim3 gS(TT / 128, TT / 128, BB);             // (16, 16, 4)
    scores_kernel<<<gS, 256, SMEM_BYTES>>>();

    softmax_kernel<<<BB * TT, 256>>>();

    dim3 gO(DD / 128, TT / 128, BB);             // (8, 16, 4)
    out_kernel<<<gO, 256, SMEM_BYTES>>>(out);
}

// round 4
// speedup vs baseline: 3.3823x; 1.1164x over previous
#include <cuda_runtime.h>
#include <cuda_bf16.h>
#include <stdint.h>
#include <math_constants.h>

#define BB 4
#define TT 2048
#define DD 1024
#define KCH 32

typedef __nv_bfloat16 bf16;

// ---- scratch (allocation-free rule: __device__ globals), bf16 hi/lo pairs ----
__device__ __align__(256) bf16 g_xh[(size_t)BB * TT * DD];
__device__ __align__(256) bf16 g_xl[(size_t)BB * TT * DD];
__device__ __align__(256) bf16 g_wh[3 * (size_t)DD * DD];
__device__ __align__(256) bf16 g_wl[3 * (size_t)DD * DD];
__device__ __align__(256) bf16 g_qh[(size_t)BB * TT * DD];
__device__ __align__(256) bf16 g_ql[(size_t)BB * TT * DD];
__device__ __align__(256) bf16 g_kh[(size_t)BB * TT * DD];
__device__ __align__(256) bf16 g_kl[(size_t)BB * TT * DD];
__device__ __align__(256) bf16 g_vh[(size_t)BB * TT * DD];
__device__ __align__(256) bf16 g_vl[(size_t)BB * TT * DD];
__device__ __align__(256) float g_S[(size_t)BB * TT * TT];
__device__ __align__(256) bf16 g_ph[(size_t)BB * TT * TT];
__device__ __align__(256) bf16 g_pl[(size_t)BB * TT * TT];

// SMEM: 3 stages x (A_hi 8K | A_lo 8K | B_hi 8K | B_lo 8K)
#define S_AH 0
#define S_AL 8192
#define S_BH 16384
#define S_BL 24576
#define STAGE 32768
#define NSTAGE 3
#define SMEM_BYTES (NSTAGE * STAGE)   // 98304

__device__ __forceinline__ uint32_t smem_u32(const void* p) {
    uint32_t a;
    asm("{ .reg .u64 t; cvta.to.shared.u64 t, %1; cvt.u32.u64 %0, t; }" : "=r"(a) : "l"(p));
    return a;
}
// 64B-row swizzle ([row][32k] tiles) and 256B-row swizzle ([32k][128n] tile)
__device__ __forceinline__ uint32_t swA(uint32_t o) { return o ^ ((o >> 3) & 0x30); }
__device__ __forceinline__ uint32_t swB(uint32_t o) { return o ^ ((o >> 4) & 0x70); }

__device__ __forceinline__ void cpa16(uint32_t dst, const void* src) {
    asm volatile("cp.async.cg.shared.global [%0], [%1], 16;" :: "r"(dst), "l"(src));
}
__device__ __forceinline__ void cpa_commit() { asm volatile("cp.async.commit_group;" ::: "memory"); }
__device__ __forceinline__ void cpa_wait1()  { asm volatile("cp.async.wait_group 1;" ::: "memory"); }

__device__ __forceinline__ void ldsm4(uint32_t addr, uint32_t r[4]) {
    asm volatile("ldmatrix.sync.aligned.m8n8.x4.shared.b16 {%0,%1,%2,%3}, [%4];"
                 : "=r"(r[0]), "=r"(r[1]), "=r"(r[2]), "=r"(r[3]) : "r"(addr));
}
__device__ __forceinline__ void ldsm4t(uint32_t addr, uint32_t r[4]) {
    asm volatile("ldmatrix.sync.aligned.m8n8.x4.trans.shared.b16 {%0,%1,%2,%3}, [%4];"
                 : "=r"(r[0]), "=r"(r[1]), "=r"(r[2]), "=r"(r[3]) : "r"(addr));
}
__device__ __forceinline__ void mma16816(float c[4], const uint32_t a[4],
                                         uint32_t b0, uint32_t b1) {
    asm volatile("mma.sync.aligned.m16n8k16.row.col.f32.bf16.bf16.f32 "
                 "{%0,%1,%2,%3}, {%4,%5,%6,%7}, {%8,%9}, {%0,%1,%2,%3};"
                 : "+f"(c[0]), "+f"(c[1]), "+f"(c[2]), "+f"(c[3])
                 : "r"(a[0]), "r"(a[1]), "r"(a[2]), "r"(a[3]), "r"(b0), "r"(b1));
}

// fp32 pair -> (hi bf16x2 word, lo bf16x2 word), lo = RN(v - float(hi))
__device__ __forceinline__ void split2(float a, float b, uint32_t& hi, uint32_t& lo) {
    __nv_bfloat162 h = __floats2bfloat162_rn(a, b);
    float ra = a - __bfloat162float(h.x);
    float rb = b - __bfloat162float(h.y);
    __nv_bfloat162 l = __floats2bfloat162_rn(ra, rb);
    hi = *reinterpret_cast<uint32_t*>(&h);
    lo = *reinterpret_cast<uint32_t*>(&l);
}

// ---------------------------------------------------------------------------
// HMMA split-bf16 GEMM, pre-split bf16 hi/lo inputs staged via cp.async.
//   BT=true : B stored [N][K] (NT);  BT=false: B stored [K][N] (NN, ldsm.trans)
//   EPI_SPLIT: write hi/lo bf16 outputs instead of fp32
// 128x128 CTA tile, 8 warps (2Mx4N), K-chunk 32, 3-stage cp.async pipeline.
// ---------------------------------------------------------------------------
template <bool BT, bool EPI_SPLIT>
__device__ __forceinline__ void gemm_mma(const bf16* __restrict__ Ahg, const bf16* __restrict__ Alg,
                                         const bf16* __restrict__ Bhg, const bf16* __restrict__ Blg,
                                         float* Cf, bf16* Chi, bf16* Clo,
                                         int Ntot, int K, float scale)
{
    extern __shared__ char smc[];
    const uint32_t sb  = smem_u32(smc);
    const int tid  = threadIdx.x;
    const int lane = tid & 31;
    const int wid  = tid >> 5;
    const int wr   = wid >> 2;
    const int wc   = wid & 3;
    const int m0   = blockIdx.y * 128;
    const int n0   = blockIdx.x * 128;

    float acc[4][4][4];
#pragma unroll
    for (int i = 0; i < 4; i++)
#pragma unroll
        for (int j = 0; j < 4; j++)
#pragma unroll
            for (int e = 0; e < 4; e++) acc[i][j][e] = 0.f;

    const int nch = K / KCH;

    // ---- stage chunk c into stage buffer s ----
    auto stage = [&](int c, int s) {
        const uint32_t base = sb + s * STAGE;
        const int k0 = c * KCH;
        // A: [128 rows][32 k]; 512 16B-chunks per component, 2 per thread
#pragma unroll
        for (int i = 0; i < 2; i++) {
            int u = tid + i * 256;
            int row = u >> 2, ch = u & 3;
            uint32_t off = swA((uint32_t)(row * 64 + ch * 16));
            const size_t ga = (size_t)(m0 + row) * K + k0 + ch * 8;
            cpa16(base + S_AH + off, Ahg + ga);
            cpa16(base + S_AL + off, Alg + ga);
        }
        if (BT) {
#pragma unroll
            for (int i = 0; i < 2; i++) {
                int u = tid + i * 256;
                int row = u >> 2, ch = u & 3;
                uint32_t off = swA((uint32_t)(row * 64 + ch * 16));
                const size_t gb = (size_t)(n0 + row) * K + k0 + ch * 8;
                cpa16(base + S_BH + off, Bhg + gb);
                cpa16(base + S_BL + off, Blg + gb);
            }
        } else {
            // B: [32 k][128 n]; rows 256B
#pragma unroll
            for (int i = 0; i < 2; i++) {
                int u = tid + i * 256;
                int kr = u >> 4, ch = u & 15;
                uint32_t off = swB((uint32_t)(kr * 256 + ch * 16));
                const size_t gb = (size_t)(k0 + kr) * Ntot + n0 + ch * 8;
                cpa16(base + S_BH + off, Bhg + gb);
                cpa16(base + S_BL + off, Blg + gb);
            }
        }
        cpa_commit();
    };

    // ---- compute one staged chunk ----
    auto compute = [&](int s) {
        const uint32_t base = sb + s * STAGE;
#pragma unroll
        for (int ks = 0; ks < KCH / 16; ks++) {
            const uint32_t aoff =
                swA((uint32_t)((wr * 64 + (lane & 15)) * 64 + (ks * 2 + (lane >> 4)) * 16));
            uint32_t Ah[4][4], Bh[2][4], Bl[2][4];
#pragma unroll
            for (int mt = 0; mt < 4; mt++)
                ldsm4(base + S_AH + aoff + mt * 1024, Ah[mt]);
            if (BT) {
                const uint32_t boff =
                    swA((uint32_t)((wc * 32 + (lane >> 4) * 8 + (lane & 7)) * 64 +
                                   (ks * 2 + ((lane >> 3) & 1)) * 16));
#pragma unroll
                for (int ng = 0; ng < 2; ng++) {
                    ldsm4(base + S_BH + boff + ng * 1024, Bh[ng]);
                    ldsm4(base + S_BL + boff + ng * 1024, Bl[ng]);
                }
            } else {
#pragma unroll
                for (int g2 = 0; g2 < 2; g2++) {
                    const uint32_t boff =
                        swB((uint32_t)((ks * 16 + (lane & 15)) * 256 +
                                       wc * 64 + (g2 * 2 + (lane >> 4)) * 16));
                    ldsm4t(base + S_BH + boff, Bh[g2]);
                    ldsm4t(base + S_BL + boff, Bl[g2]);
                }
            }
            // pass 1: hi*hi
#pragma unroll
            for (int mt = 0; mt < 4; mt++)
#pragma unroll
                for (int ng = 0; ng < 2; ng++) {
                    mma16816(acc[mt][ng * 2],     Ah[mt], Bh[ng][0], Bh[ng][1]);
                    mma16816(acc[mt][ng * 2 + 1], Ah[mt], Bh[ng][2], Bh[ng][3]);
                }
            // pass 2: hi*lo
#pragma unroll
            for (int mt = 0; mt < 4; mt++)
#pragma unroll
                for (int ng = 0; ng < 2; ng++) {
                    mma16816(acc[mt][ng * 2],     Ah[mt], Bl[ng][0], Bl[ng][1]);
                    mma16816(acc[mt][ng * 2 + 1], Ah[mt], Bl[ng][2], Bl[ng][3]);
                }
            // pass 3: lo*hi (A_lo loaded late to cap register pressure)
            uint32_t Al[4][4];
#pragma unroll
            for (int mt = 0; mt < 4; mt++)
                ldsm4(base + S_AL + aoff + mt * 1024, Al[mt]);
#pragma unroll
            for (int mt = 0; mt < 4; mt++)
#pragma unroll
                for (int ng = 0; ng < 2; ng++) {
                    mma16816(acc[mt][ng * 2],     Al[mt], Bh[ng][0], Bh[ng][1]);
                    mma16816(acc[mt][ng * 2 + 1], Al[mt], Bh[ng][2], Bh[ng][3]);
                }
        }
    };

    stage(0, 0);
    if (nch > 1) stage(1, 1);
    for (int c = 0; c < nch; c++) {
        cpa_wait1();                       // own stage-c ops landed
        __syncthreads();                   // all warps' stage-c visible; compute(c-1) done
        if (c + 2 < nch) stage(c + 2, (c + 2) % NSTAGE);
        compute(c % NSTAGE);
    }

    // ---- epilogue ----
#pragma unroll
    for (int mt = 0; mt < 4; mt++)
#pragma unroll
        for (int nt = 0; nt < 4; nt++) {
            const float* a4 = acc[mt][nt];
            const int r   = m0 + wr * 64 + mt * 16 + (lane >> 2);
            const int col = n0 + wc * 32 + nt * 8 + (lane & 3) * 2;
            if (EPI_SPLIT) {
                uint32_t h, l;
                split2(a4[0] * scale, a4[1] * scale, h, l);
                *(uint32_t*)(Chi + (size_t)r * Ntot + col) = h;
                *(uint32_t*)(Clo + (size_t)r * Ntot + col) = l;
                split2(a4[2] * scale, a4[3] * scale, h, l);
                *(uint32_t*)(Chi + (size_t)(r + 8) * Ntot + col) = h;
                *(uint32_t*)(Clo + (size_t)(r + 8) * Ntot + col) = l;
            } else {
                *(float2*)(Cf + (size_t)r * Ntot + col) =
                    make_float2(a4[0] * scale, a4[1] * scale);
                *(float2*)(Cf + (size_t)(r + 8) * Ntot + col) =
                    make_float2(a4[2] * scale, a4[3] * scale);
            }
        }
}

// ---------------------------------------------------------------------------
// fp32 -> hi/lo bf16 elementwise split (x and W preprocessing)
__global__ __launch_bounds__(256) void split_kernel(const float* __restrict__ in,
                                                    bf16* __restrict__ hi,
                                                    bf16* __restrict__ lo, int n4)
{
    int i = blockIdx.x * 256 + threadIdx.x;
    if (i >= n4) return;
    float4 v = ((const float4*)in)[i];
    uint32_t h0, l0, h1, l1;
    split2(v.x, v.y, h0, l0);
    split2(v.z, v.w, h1, l1);
    ((uint2*)hi)[i] = make_uint2(h0, h1);
    ((uint2*)lo)[i] = make_uint2(l0, l1);
}

__global__ __launch_bounds__(256, 2) void qkv_kernel()
{
    const int z = blockIdx.z;
    bf16* outh = (z == 0) ? g_qh : (z == 1) ? g_kh : g_vh;
    bf16* outl = (z == 0) ? g_ql : (z == 1) ? g_kl : g_vl;
    gemm_mma<true, true>(g_xh, g_xl,
                         g_wh + (size_t)z * DD * DD, g_wl + (size_t)z * DD * DD,
                         nullptr, outh, outl, DD, DD, 1.0f);
}

__global__ __launch_bounds__(256, 2) void scores_kernel()
{
    const int b = blockIdx.z;
    gemm_mma<true, false>(g_qh + (size_t)b * TT * DD, g_ql + (size_t)b * TT * DD,
                          g_kh + (size_t)b * TT * DD, g_kl + (size_t)b * TT * DD,
                          g_S + (size_t)b * TT * TT, nullptr, nullptr,
                          TT, DD, 0.03125f /* 1/sqrt(1024) */);
}

__global__ __launch_bounds__(256, 2) void out_kernel(float* __restrict__ out)
{
    const int b = blockIdx.z;
    gemm_mma<false, false>(g_ph + (size_t)b * TT * TT, g_pl + (size_t)b * TT * TT,
                           g_vh + (size_t)b * TT * DD, g_vl + (size_t)b * TT * DD,
                           out + (size_t)b * TT * DD, nullptr, nullptr,
                           DD, TT, 1.0f);
}

// Row softmax: g_S fp32 -> probabilities as hi/lo bf16 (g_ph, g_pl)
__global__ __launch_bounds__(256) void softmax_kernel()
{
    const size_t row = blockIdx.x;
    const float* r = g_S + row * TT;
    const int t = threadIdx.x;

    float v[8];
#pragma unroll
    for (int i = 0; i < 8; i++) v[i] = r[t + i * 256];

    float m = -CUDART_INF_F;
#pragma unroll
    for (int i = 0; i < 8; i++) m = fmaxf(m, v[i]);

    __shared__ float red[256];
    red[t] = m;
    __syncthreads();
    for (int s = 128; s > 0; s >>= 1) {
        if (t < s) red[t] = fmaxf(red[t], red[t + s]);
        __syncthreads();
    }
    m = red[0];
    __syncthreads();

    float sum = 0.f;
#pragma unroll
    for (int i = 0; i < 8; i++) { v[i] = __expf(v[i] - m); sum += v[i]; }
    red[t] = sum;
    __syncthreads();
    for (int s = 128; s > 0; s >>= 1) {
        if (t < s) red[t] += red[t + s];
        __syncthreads();
    }
    const float inv = 1.0f / red[0];

    bf16* ph = g_ph + row * TT;
    bf16* pl = g_pl + row * TT;
#pragma unroll
    for (int i = 0; i < 8; i++) {
        float p = v[i] * inv;
        __nv_bfloat16 h = __float2bfloat16_rn(p);
        __nv_bfloat16 l = __float2bfloat16_rn(p - __bfloat162float(h));
        ph[t + i * 256] = h;
        pl[t + i * 256] = l;
    }
}

extern "C" void kernel_launch(void* const* d_in, const int* in_sizes, int n_in,
                              void* d_out, int out_size)
{
    (void)in_sizes; (void)n_in; (void)out_size;
    const float* x  = (const float*)d_in[0];
    const float* Wq = (const float*)d_in[1];
    const float* Wk = (const float*)d_in[2];
    const float* Wv = (const float*)d_in[3];
    float* out = (float*)d_out;

    cudaFuncSetAttribute(qkv_kernel,    cudaFuncAttributeMaxDynamicSharedMemorySize, SMEM_BYTES);
    cudaFuncSetAttribute(scores_kernel, cudaFuncAttributeMaxDynamicSharedMemorySize, SMEM_BYTES);
    cudaFuncSetAttribute(out_kernel,    cudaFuncAttributeMaxDynamicSharedMemorySize, SMEM_BYTES);

    bf16 *xh, *xl, *wh, *wl;
    cudaGetSymbolAddress((void**)&xh, g_xh);
    cudaGetSymbolAddress((void**)&xl, g_xl);
    cudaGetSymbolAddress((void**)&wh, g_wh);
    cudaGetSymbolAddress((void**)&wl, g_wl);

    // preprocess: split x and W into bf16 hi/lo
    const int nx4 = BB * TT * DD / 4;          // 2,097,152
    const int nw4 = DD * DD / 4;               //   262,144
    split_kernel<<<(nx4 + 255) / 256, 256>>>(x, xh, xl, nx4);
    split_kernel<<<(nw4 + 255) / 256, 256>>>(Wq, wh, wl, nw4);
    split_kernel<<<(nw4 + 255) / 256, 256>>>(Wk, wh + (size_t)DD * DD, wl + (size_t)DD * DD, nw4);
    split_kernel<<<(nw4 + 255) / 256, 256>>>(Wv, wh + 2 * (size_t)DD * DD, wl + 2 * (size_t)DD * DD, nw4);

    dim3 gQKV(DD / 128, (BB * TT) / 128, 3);   // (8, 64, 3)
    qkv_kernel<<<gQKV, 256, SMEM_BYTES>>>();

    dim3 gS(TT / 128, TT / 128, BB);           // (16, 16, 4)
    scores_kernel<<<gS, 256, SMEM_BYTES>>>();

    softmax_kernel<<<BB * TT, 256>>>();

    dim3 gO(DD / 128, TT / 128, BB);           // (8, 16, 4)
    out_kernel<<<gO, 256, SMEM_BYTES>>>(out);
}

// round 5
// speedup vs baseline: 3.4128x; 1.0090x over previous
#include <cuda_runtime.h>
#include <cuda_bf16.h>
#include <stdint.h>
#include <math_constants.h>

#define BB 4
#define TT 2048
#define DD 1024
#define KCH 32

typedef __nv_bfloat16 bf16;

// ---- scratch (allocation-free rule: __device__ globals), bf16 hi/lo pairs ----
__device__ __align__(256) bf16 g_xh[(size_t)BB * TT * DD];
__device__ __align__(256) bf16 g_xl[(size_t)BB * TT * DD];
__device__ __align__(256) bf16 g_wh[3 * (size_t)DD * DD];
__device__ __align__(256) bf16 g_wl[3 * (size_t)DD * DD];
__device__ __align__(256) bf16 g_qh[(size_t)BB * TT * DD];
__device__ __align__(256) bf16 g_ql[(size_t)BB * TT * DD];
__device__ __align__(256) bf16 g_kh[(size_t)BB * TT * DD];
__device__ __align__(256) bf16 g_kl[(size_t)BB * TT * DD];
__device__ __align__(256) bf16 g_vh[(size_t)BB * TT * DD];
__device__ __align__(256) bf16 g_vl[(size_t)BB * TT * DD];
__device__ __align__(256) float g_S[(size_t)BB * TT * TT];
__device__ __align__(256) bf16 g_ph[(size_t)BB * TT * TT];
__device__ __align__(256) bf16 g_pl[(size_t)BB * TT * TT];

// SMEM: 3 stages x (A_hi 8K | A_lo 8K | B_hi 8K | B_lo 8K)
#define S_AH 0
#define S_AL 8192
#define S_BH 16384
#define S_BL 24576
#define STAGE 32768
#define NSTAGE 3
#define SMEM_BYTES (NSTAGE * STAGE)   // 98304

__device__ __forceinline__ uint32_t smem_u32(const void* p) {
    uint32_t a;
    asm("{ .reg .u64 t; cvta.to.shared.u64 t, %1; cvt.u32.u64 %0, t; }" : "=r"(a) : "l"(p));
    return a;
}
// 64B-row swizzle ([row][32k] tiles) and 256B-row swizzle ([32k][128n] tile)
__device__ __forceinline__ uint32_t swA(uint32_t o) { return o ^ ((o >> 3) & 0x30); }
__device__ __forceinline__ uint32_t swB(uint32_t o) { return o ^ ((o >> 4) & 0x70); }

__device__ __forceinline__ void cpa16(uint32_t dst, const void* src) {
    asm volatile("cp.async.cg.shared.global [%0], [%1], 16;" :: "r"(dst), "l"(src));
}
__device__ __forceinline__ void cpa_commit() { asm volatile("cp.async.commit_group;" ::: "memory"); }
__device__ __forceinline__ void cpa_wait1()  { asm volatile("cp.async.wait_group 1;" ::: "memory"); }

__device__ __forceinline__ void ldsm4(uint32_t addr, uint32_t r[4]) {
    asm volatile("ldmatrix.sync.aligned.m8n8.x4.shared.b16 {%0,%1,%2,%3}, [%4];"
                 : "=r"(r[0]), "=r"(r[1]), "=r"(r[2]), "=r"(r[3]) : "r"(addr));
}
__device__ __forceinline__ void ldsm4t(uint32_t addr, uint32_t r[4]) {
    asm volatile("ldmatrix.sync.aligned.m8n8.x4.trans.shared.b16 {%0,%1,%2,%3}, [%4];"
                 : "=r"(r[0]), "=r"(r[1]), "=r"(r[2]), "=r"(r[3]) : "r"(addr));
}
__device__ __forceinline__ void mma16816(float c[4], const uint32_t a[4],
                                         uint32_t b0, uint32_t b1) {
    asm volatile("mma.sync.aligned.m16n8k16.row.col.f32.bf16.bf16.f32 "
                 "{%0,%1,%2,%3}, {%4,%5,%6,%7}, {%8,%9}, {%0,%1,%2,%3};"
                 : "+f"(c[0]), "+f"(c[1]), "+f"(c[2]), "+f"(c[3])
                 : "r"(a[0]), "r"(a[1]), "r"(a[2]), "r"(a[3]), "r"(b0), "r"(b1));
}

// fp32 pair -> (hi bf16x2 word, lo bf16x2 word), lo = RN(v - float(hi))
__device__ __forceinline__ void split2(float a, float b, uint32_t& hi, uint32_t& lo) {
    __nv_bfloat162 h = __floats2bfloat162_rn(a, b);
    float ra = a - __bfloat162float(h.x);
    float rb = b - __bfloat162float(h.y);
    __nv_bfloat162 l = __floats2bfloat162_rn(ra, rb);
    hi = *reinterpret_cast<uint32_t*>(&h);
    lo = *reinterpret_cast<uint32_t*>(&l);
}

// ---------------------------------------------------------------------------
// HMMA split-bf16 GEMM, pre-split bf16 hi/lo inputs staged via cp.async.
//   BT=true : B stored [N][K] (NT);  BT=false: B stored [K][N] (NN, ldsm.trans)
//   EPI_SPLIT: write hi/lo bf16 outputs instead of fp32
// 128x128 CTA tile, 4 warps (2x2 -> 64x64 warp tile), K-chunk 32,
// 3-stage cp.async pipeline. 64x64 warp tile halves SMEM bytes per MAC.
// ---------------------------------------------------------------------------
template <bool BT, bool EPI_SPLIT>
__device__ __forceinline__ void gemm_mma(const bf16* __restrict__ Ahg, const bf16* __restrict__ Alg,
                                         const bf16* __restrict__ Bhg, const bf16* __restrict__ Blg,
                                         float* Cf, bf16* Chi, bf16* Clo,
                                         int Ntot, int K, float scale)
{
    extern __shared__ char smc[];
    const uint32_t sb  = smem_u32(smc);
    const int tid  = threadIdx.x;
    const int lane = tid & 31;
    const int wid  = tid >> 5;          // 0..3
    const int wr   = wid >> 1;          // warp row -> m offset wr*64
    const int wc   = wid & 1;           // warp col -> n offset wc*64
    const int m0   = blockIdx.y * 128;
    const int n0   = blockIdx.x * 128;

    float acc[4][8][4];
#pragma unroll
    for (int i = 0; i < 4; i++)
#pragma unroll
        for (int j = 0; j < 8; j++)
#pragma unroll
            for (int e = 0; e < 4; e++) acc[i][j][e] = 0.f;

    const int nch = K / KCH;

    // ---- stage chunk c into stage buffer s (128 threads) ----
    auto stage = [&](int c, int s) {
        const uint32_t base = sb + s * STAGE;
        const int k0 = c * KCH;
        // A: [128 rows][32 k] = 512 16B-chunks per component; 4 per thread
#pragma unroll
        for (int i = 0; i < 4; i++) {
            int u = tid + i * 128;
            int row = u >> 2, ch = u & 3;
            uint32_t off = swA((uint32_t)(row * 64 + ch * 16));
            const size_t ga = (size_t)(m0 + row) * K + k0 + ch * 8;
            cpa16(base + S_AH + off, Ahg + ga);
            cpa16(base + S_AL + off, Alg + ga);
        }
        if (BT) {
#pragma unroll
            for (int i = 0; i < 4; i++) {
                int u = tid + i * 128;
                int row = u >> 2, ch = u & 3;
                uint32_t off = swA((uint32_t)(row * 64 + ch * 16));
                const size_t gb = (size_t)(n0 + row) * K + k0 + ch * 8;
                cpa16(base + S_BH + off, Bhg + gb);
                cpa16(base + S_BL + off, Blg + gb);
            }
        } else {
            // B: [32 k][128 n]; rows 256B
#pragma unroll
            for (int i = 0; i < 4; i++) {
                int u = tid + i * 128;
                int kr = u >> 4, ch = u & 15;
                uint32_t off = swB((uint32_t)(kr * 256 + ch * 16));
                const size_t gb = (size_t)(k0 + kr) * Ntot + n0 + ch * 8;
                cpa16(base + S_BH + off, Bhg + gb);
                cpa16(base + S_BL + off, Blg + gb);
            }
        }
        cpa_commit();
    };

    // ---- compute one staged chunk ----
    auto compute = [&](int s) {
        const uint32_t base = sb + s * STAGE;
#pragma unroll
        for (int ks = 0; ks < KCH / 16; ks++) {
            const uint32_t aoff =
                swA((uint32_t)((wr * 64 + (lane & 15)) * 64 + (ks * 2 + (lane >> 4)) * 16));
            uint32_t Ah[4][4], Bh[4][4], Bl[4][4];
#pragma unroll
            for (int mt = 0; mt < 4; mt++)
                ldsm4(base + S_AH + aoff + mt * 1024, Ah[mt]);
            if (BT) {
                const uint32_t boff =
                    swA((uint32_t)((wc * 64 + (lane >> 4) * 8 + (lane & 7)) * 64 +
                                   (ks * 2 + ((lane >> 3) & 1)) * 16));
#pragma unroll
                for (int ng = 0; ng < 4; ng++) {       // 16 n-rows per group
                    ldsm4(base + S_BH + boff + ng * 1024, Bh[ng]);
                    ldsm4(base + S_BL + boff + ng * 1024, Bl[ng]);
                }
            } else {
#pragma unroll
                for (int ng = 0; ng < 4; ng++) {
                    const uint32_t boff =
                        swB((uint32_t)((ks * 16 + (lane & 15)) * 256 +
                                       wc * 128 + (ng * 2 + (lane >> 4)) * 16));
                    ldsm4t(base + S_BH + boff, Bh[ng]);
                    ldsm4t(base + S_BL + boff, Bl[ng]);
                }
            }
            // pass 1: hi*hi
#pragma unroll
            for (int mt = 0; mt < 4; mt++)
#pragma unroll
                for (int ng = 0; ng < 4; ng++) {
                    mma16816(acc[mt][ng * 2],     Ah[mt], Bh[ng][0], Bh[ng][1]);
                    mma16816(acc[mt][ng * 2 + 1], Ah[mt], Bh[ng][2], Bh[ng][3]);
                }
            // pass 2: hi*lo
#pragma unroll
            for (int mt = 0; mt < 4; mt++)
#pragma unroll
                for (int ng = 0; ng < 4; ng++) {
                    mma16816(acc[mt][ng * 2],     Ah[mt], Bl[ng][0], Bl[ng][1]);
                    mma16816(acc[mt][ng * 2 + 1], Ah[mt], Bl[ng][2], Bl[ng][3]);
                }
            // pass 3: lo*hi (A_lo loaded late to cap register pressure)
            uint32_t Al[4][4];
#pragma unroll
            for (int mt = 0; mt < 4; mt++)
                ldsm4(base + S_AL + aoff + mt * 1024, Al[mt]);
#pragma unroll
            for (int mt = 0; mt < 4; mt++)
#pragma unroll
                for (int ng = 0; ng < 4; ng++) {
                    mma16816(acc[mt][ng * 2],     Al[mt], Bh[ng][0], Bh[ng][1]);
                    mma16816(acc[mt][ng * 2 + 1], Al[mt], Bh[ng][2], Bh[ng][3]);
                }
        }
    };

    stage(0, 0);
    if (nch > 1) stage(1, 1);
    for (int c = 0; c < nch; c++) {
        cpa_wait1();                       // stage-c ops landed
        __syncthreads();                   // all warps' stage-c visible; compute(c-1) done
        if (c + 2 < nch) stage(c + 2, (c + 2) % NSTAGE);
        compute(c % NSTAGE);
    }

    // ---- epilogue ----
#pragma unroll
    for (int mt = 0; mt < 4; mt++)
#pragma unroll
        for (int nt = 0; nt < 8; nt++) {
            const float* a4 = acc[mt][nt];
            const int r   = m0 + wr * 64 + mt * 16 + (lane >> 2);
            const int col = n0 + wc * 64 + nt * 8 + (lane & 3) * 2;
            if (EPI_SPLIT) {
                uint32_t h, l;
                split2(a4[0] * scale, a4[1] * scale, h, l);
                *(uint32_t*)(Chi + (size_t)r * Ntot + col) = h;
                *(uint32_t*)(Clo + (size_t)r * Ntot + col) = l;
                split2(a4[2] * scale, a4[3] * scale, h, l);
                *(uint32_t*)(Chi + (size_t)(r + 8) * Ntot + col) = h;
                *(uint32_t*)(Clo + (size_t)(r + 8) * Ntot + col) = l;
            } else {
                *(float2*)(Cf + (size_t)r * Ntot + col) =
                    make_float2(a4[0] * scale, a4[1] * scale);
                *(float2*)(Cf + (size_t)(r + 8) * Ntot + col) =
                    make_float2(a4[2] * scale, a4[3] * scale);
            }
        }
}

// ---------------------------------------------------------------------------
// fp32 -> hi/lo bf16 elementwise split (x and W preprocessing)
__global__ __launch_bounds__(256) void split_kernel(const float* __restrict__ in,
                                                    bf16* __restrict__ hi,
                                                    bf16* __restrict__ lo, int n4)
{
    int i = blockIdx.x * 256 + threadIdx.x;
    if (i >= n4) return;
    float4 v = ((const float4*)in)[i];
    uint32_t h0, l0, h1, l1;
    split2(v.x, v.y, h0, l0);
    split2(v.z, v.w, h1, l1);
    ((uint2*)hi)[i] = make_uint2(h0, h1);
    ((uint2*)lo)[i] = make_uint2(l0, l1);
}

__global__ __launch_bounds__(128, 2) void qkv_kernel()
{
    const int z = blockIdx.z;
    bf16* outh = (z == 0) ? g_qh : (z == 1) ? g_kh : g_vh;
    bf16* outl = (z == 0) ? g_ql : (z == 1) ? g_kl : g_vl;
    gemm_mma<true, true>(g_xh, g_xl,
                         g_wh + (size_t)z * DD * DD, g_wl + (size_t)z * DD * DD,
                         nullptr, outh, outl, DD, DD, 1.0f);
}

__global__ __launch_bounds__(128, 2) void scores_kernel()
{
    const int b = blockIdx.z;
    gemm_mma<true, false>(g_qh + (size_t)b * TT * DD, g_ql + (size_t)b * TT * DD,
                          g_kh + (size_t)b * TT * DD, g_kl + (size_t)b * TT * DD,
                          g_S + (size_t)b * TT * TT, nullptr, nullptr,
                          TT, DD, 0.03125f /* 1/sqrt(1024) */);
}

__global__ __launch_bounds__(128, 2) void out_kernel(float* __restrict__ out)
{
    const int b = blockIdx.z;
    gemm_mma<false, false>(g_ph + (size_t)b * TT * TT, g_pl + (size_t)b * TT * TT,
                           g_vh + (size_t)b * TT * DD, g_vl + (size_t)b * TT * DD,
                           out + (size_t)b * TT * DD, nullptr, nullptr,
                           DD, TT, 1.0f);
}

// Row softmax: g_S fp32 -> probabilities as hi/lo bf16 (g_ph, g_pl)
__global__ __launch_bounds__(256) void softmax_kernel()
{
    const size_t row = blockIdx.x;
    const float* r = g_S + row * TT;
    const int t = threadIdx.x;

    float v[8];
#pragma unroll
    for (int i = 0; i < 8; i++) v[i] = r[t + i * 256];

    float m = -CUDART_INF_F;
#pragma unroll
    for (int i = 0; i < 8; i++) m = fmaxf(m, v[i]);

    __shared__ float red[256];
    red[t] = m;
    __syncthreads();
    for (int s = 128; s > 0; s >>= 1) {
        if (t < s) red[t] = fmaxf(red[t], red[t + s]);
        __syncthreads();
    }
    m = red[0];
    __syncthreads();

    float sum = 0.f;
#pragma unroll
    for (int i = 0; i < 8; i++) { v[i] = __expf(v[i] - m); sum += v[i]; }
    red[t] = sum;
    __syncthreads();
    for (int s = 128; s > 0; s >>= 1) {
        if (t < s) red[t] += red[t + s];
        __syncthreads();
    }
    const float inv = 1.0f / red[0];

    bf16* ph = g_ph + row * TT;
    bf16* pl = g_pl + row * TT;
#pragma unroll
    for (int i = 0; i < 8; i++) {
        float p = v[i] * inv;
        __nv_bfloat16 h = __float2bfloat16_rn(p);
        __nv_bfloat16 l = __float2bfloat16_rn(p - __bfloat162float(h));
        ph[t + i * 256] = h;
        pl[t + i * 256] = l;
    }
}

extern "C" void kernel_launch(void* const* d_in, const int* in_sizes, int n_in,
                              void* d_out, int out_size)
{
    (void)in_sizes; (void)n_in; (void)out_size;
    const float* x  = (const float*)d_in[0];
    const float* Wq = (const float*)d_in[1];
    const float* Wk = (const float*)d_in[2];
    const float* Wv = (const float*)d_in[3];
    float* out = (float*)d_out;

    cudaFuncSetAttribute(qkv_kernel,    cudaFuncAttributeMaxDynamicSharedMemorySize, SMEM_BYTES);
    cudaFuncSetAttribute(scores_kernel, cudaFuncAttributeMaxDynamicSharedMemorySize, SMEM_BYTES);
    cudaFuncSetAttribute(out_kernel,    cudaFuncAttributeMaxDynamicSharedMemorySize, SMEM_BYTES);

    bf16 *xh, *xl, *wh, *wl;
    cudaGetSymbolAddress((void**)&xh, g_xh);
    cudaGetSymbolAddress((void**)&xl, g_xl);
    cudaGetSymbolAddress((void**)&wh, g_wh);
    cudaGetSymbolAddress((void**)&wl, g_wl);

    // preprocess: split x and W into bf16 hi/lo
    const int nx4 = BB * TT * DD / 4;          // 2,097,152
    const int nw4 = DD * DD / 4;               //   262,144
    split_kernel<<<(nx4 + 255) / 256, 256>>>(x, xh, xl, nx4);
    split_kernel<<<(nw4 + 255) / 256, 256>>>(Wq, wh, wl, nw4);
    split_kernel<<<(nw4 + 255) / 256, 256>>>(Wk, wh + (size_t)DD * DD, wl + (size_t)DD * DD, nw4);
    split_kernel<<<(nw4 + 255) / 256, 256>>>(Wv, wh + 2 * (size_t)DD * DD, wl + 2 * (size_t)DD * DD, nw4);

    dim3 gQKV(DD / 128, (BB * TT) / 128, 3);   // (8, 64, 3)
    qkv_kernel<<<gQKV, 128, SMEM_BYTES>>>();

    dim3 gS(TT / 128, TT / 128, BB);           // (16, 16, 4)
    scores_kernel<<<gS, 128, SMEM_BYTES>>>();

    softmax_kernel<<<BB * TT, 256>>>();

    dim3 gO(DD / 128, TT / 128, BB);           // (8, 16, 4)
    out_kernel<<<gO, 128, SMEM_BYTES>>>(out);
}

// round 6
// speedup vs baseline: 4.0488x; 1.1863x over previous
#include <cuda_runtime.h>
#include <cuda_bf16.h>
#include <stdint.h>
#include <math_constants.h>

#define BB 4
#define TT 2048
#define DD 1024
#define KCH 32

typedef __nv_bfloat16 bf16;

// ---- scratch (allocation-free rule: __device__ globals) ----
__device__ __align__(256) float g_x32[(size_t)BB * TT * DD];   // tf32-rounded x
__device__ __align__(256) float g_w32[2 * (size_t)DD * DD];    // tf32-rounded Wq,Wk
__device__ __align__(256) float g_q32[(size_t)BB * TT * DD];   // tf32-rounded Q
__device__ __align__(256) float g_k32[(size_t)BB * TT * DD];   // tf32-rounded K
__device__ __align__(256) bf16 g_xh[(size_t)BB * TT * DD];
__device__ __align__(256) bf16 g_xl[(size_t)BB * TT * DD];
__device__ __align__(256) bf16 g_wvh[(size_t)DD * DD];
__device__ __align__(256) bf16 g_wvl[(size_t)DD * DD];
__device__ __align__(256) bf16 g_vh[(size_t)BB * TT * DD];
__device__ __align__(256) bf16 g_vl[(size_t)BB * TT * DD];
__device__ __align__(256) float g_S[(size_t)BB * TT * TT];
__device__ __align__(256) bf16 g_ph[(size_t)BB * TT * TT];
__device__ __align__(256) bf16 g_pl[(size_t)BB * TT * TT];

// bf16 path SMEM: 3 stages x (A_hi 8K | A_lo 8K | B_hi 8K | B_lo 8K)
#define S_AH 0
#define S_AL 8192
#define S_BH 16384
#define S_BL 24576
#define STAGE 32768
#define NSTAGE 3
#define SMEM_BYTES (NSTAGE * STAGE)   // 98304 (tf32 path uses same footprint)

__device__ __forceinline__ uint32_t smem_u32(const void* p) {
    uint32_t a;
    asm("{ .reg .u64 t; cvta.to.shared.u64 t, %1; cvt.u32.u64 %0, t; }" : "=r"(a) : "l"(p));
    return a;
}
__device__ __forceinline__ uint32_t swA(uint32_t o) { return o ^ ((o >> 3) & 0x30); }
__device__ __forceinline__ uint32_t swB(uint32_t o) { return o ^ ((o >> 4) & 0x70); }

__device__ __forceinline__ void cpa16(uint32_t dst, const void* src) {
    asm volatile("cp.async.cg.shared.global [%0], [%1], 16;" :: "r"(dst), "l"(src));
}
__device__ __forceinline__ void cpa_commit() { asm volatile("cp.async.commit_group;" ::: "memory"); }
__device__ __forceinline__ void cpa_wait1()  { asm volatile("cp.async.wait_group 1;" ::: "memory"); }

__device__ __forceinline__ void ldsm4(uint32_t addr, uint32_t r[4]) {
    asm volatile("ldmatrix.sync.aligned.m8n8.x4.shared.b16 {%0,%1,%2,%3}, [%4];"
                 : "=r"(r[0]), "=r"(r[1]), "=r"(r[2]), "=r"(r[3]) : "r"(addr));
}
__device__ __forceinline__ void ldsm4t(uint32_t addr, uint32_t r[4]) {
    asm volatile("ldmatrix.sync.aligned.m8n8.x4.trans.shared.b16 {%0,%1,%2,%3}, [%4];"
                 : "=r"(r[0]), "=r"(r[1]), "=r"(r[2]), "=r"(r[3]) : "r"(addr));
}
__device__ __forceinline__ void mma16816(float c[4], const uint32_t a[4],
                                         uint32_t b0, uint32_t b1) {
    asm volatile("mma.sync.aligned.m16n8k16.row.col.f32.bf16.bf16.f32 "
                 "{%0,%1,%2,%3}, {%4,%5,%6,%7}, {%8,%9}, {%0,%1,%2,%3};"
                 : "+f"(c[0]), "+f"(c[1]), "+f"(c[2]), "+f"(c[3])
                 : "r"(a[0]), "r"(a[1]), "r"(a[2]), "r"(a[3]), "r"(b0), "r"(b1));
}
__device__ __forceinline__ void mma_tf32(float c[4], const uint32_t a[4],
                                         uint32_t b0, uint32_t b1) {
    asm volatile("mma.sync.aligned.m16n8k8.row.col.f32.tf32.tf32.f32 "
                 "{%0,%1,%2,%3}, {%4,%5,%6,%7}, {%8,%9}, {%0,%1,%2,%3};"
                 : "+f"(c[0]), "+f"(c[1]), "+f"(c[2]), "+f"(c[3])
                 : "r"(a[0]), "r"(a[1]), "r"(a[2]), "r"(a[3]), "r"(b0), "r"(b1));
}
__device__ __forceinline__ uint32_t lds32(uint32_t addr) {
    uint32_t v;
    asm volatile("ld.shared.b32 %0, [%1];" : "=r"(v) : "r"(addr));
    return v;
}
__device__ __forceinline__ float tf32_rna(float v) {
    uint32_t o;
    asm("cvt.rna.tf32.f32 %0, %1;" : "=r"(o) : "f"(v));
    return __uint_as_float(o);
}
__device__ __forceinline__ void split2(float a, float b, uint32_t& hi, uint32_t& lo) {
    __nv_bfloat162 h = __floats2bfloat162_rn(a, b);
    float ra = a - __bfloat162float(h.x);
    float rb = b - __bfloat162float(h.y);
    __nv_bfloat162 l = __floats2bfloat162_rn(ra, rb);
    hi = *reinterpret_cast<uint32_t*>(&h);
    lo = *reinterpret_cast<uint32_t*>(&l);
}

// ---------------------------------------------------------------------------
// 1xTF32 GEMM (NT): C[m,n] = scale * sum_k A[m,k]*B[n,k], fp32 operands
// already tf32-rounded. 128x128 CTA, 4 warps (2x2 -> 64x64), KCH=32 fp32,
// 3-stage cp.async. Fragments via LDS.32 (sw128 keeps all 32 lanes distinct banks).
// ---------------------------------------------------------------------------
template <bool ROUND_OUT>
__device__ __forceinline__ void gemm_tf32(const float* __restrict__ A,
                                          const float* __restrict__ Bm,
                                          float* __restrict__ C,
                                          int Ntot, int K, float scale)
{
    extern __shared__ char smc[];
    const uint32_t sb  = smem_u32(smc);
    const int tid  = threadIdx.x;
    const int lane = tid & 31;
    const int wid  = tid >> 5;
    const int wr   = wid >> 1;
    const int wc   = wid & 1;
    const int m0   = blockIdx.y * 128;
    const int n0   = blockIdx.x * 128;

    float acc[4][8][4];
#pragma unroll
    for (int i = 0; i < 4; i++)
#pragma unroll
        for (int j = 0; j < 8; j++)
#pragma unroll
            for (int e = 0; e < 4; e++) acc[i][j][e] = 0.f;

    const int nch = K / KCH;

    // stage: A,B tiles [128 rows][32 floats]=128B rows, sw128; 8 chunks/row
    auto stage = [&](int c, int s) {
        const uint32_t base = sb + s * STAGE;
        const int k0 = c * KCH;
#pragma unroll
        for (int i = 0; i < 8; i++) {
            int u = tid + i * 128;
            int row = u >> 3, ch = u & 7;
            uint32_t off = (uint32_t)(row * 128 + ((ch * 16) ^ ((row & 7) * 16)));
            cpa16(base + off,         A  + (size_t)(m0 + row) * K + k0 + ch * 4);
            cpa16(base + 16384 + off, Bm + (size_t)(n0 + row) * K + k0 + ch * 4);
        }
        cpa_commit();
    };

    const int ar  = lane >> 2;          // 0..7
    const int ac4 = (lane & 3) * 4;     // byte col within k8 group
    const uint32_t xr = (uint32_t)(ar * 16);   // sw128 XOR term (lane constant)
    uint32_t rA[4], rB[8];
#pragma unroll
    for (int mt = 0; mt < 4; mt++) rA[mt] = (uint32_t)((wr * 64 + mt * 16 + ar) * 128);
#pragma unroll
    for (int nt = 0; nt < 8; nt++) rB[nt] = (uint32_t)((wc * 64 + nt * 8 + ar) * 128);

    auto compute = [&](int s) {
        const uint32_t base  = sb + s * STAGE;
        const uint32_t baseB = base + 16384;
#pragma unroll
        for (int ks = 0; ks < 4; ks++) {                 // k8 slices of KCH=32
            const uint32_t c0 = (uint32_t)(ks * 32 + ac4);
            const uint32_t c1 = c0 + 16;
            const uint32_t o0 = c0 ^ xr, o1 = c1 ^ xr;
            uint32_t a[4][4];
#pragma unroll
            for (int mt = 0; mt < 4; mt++) {
                a[mt][0] = lds32(base + rA[mt] + o0);
                a[mt][1] = lds32(base + rA[mt] + 1024 + o0);   // row+8
                a[mt][2] = lds32(base + rA[mt] + o1);
                a[mt][3] = lds32(base + rA[mt] + 1024 + o1);
            }
#pragma unroll
            for (int nt = 0; nt < 8; nt++) {
                uint32_t b0 = lds32(baseB + rB[nt] + o0);
                uint32_t b1 = lds32(baseB + rB[nt] + o1);
#pragma unroll
                for (int mt = 0; mt < 4; mt++)
                    mma_tf32(acc[mt][nt], a[mt], b0, b1);
            }
        }
    };

    stage(0, 0);
    if (nch > 1) stage(1, 1);
    for (int c = 0; c < nch; c++) {
        cpa_wait1();
        __syncthreads();
        if (c + 2 < nch) stage(c + 2, (c + 2) % NSTAGE);
        compute(c % NSTAGE);
    }

#pragma unroll
    for (int mt = 0; mt < 4; mt++)
#pragma unroll
        for (int nt = 0; nt < 8; nt++) {
            const float* a4 = acc[mt][nt];
            const int r   = m0 + wr * 64 + mt * 16 + (lane >> 2);
            const int col = n0 + wc * 64 + nt * 8 + (lane & 3) * 2;
            float2 v0 = make_float2(a4[0] * scale, a4[1] * scale);
            float2 v1 = make_float2(a4[2] * scale, a4[3] * scale);
            if (ROUND_OUT) {
                v0.x = tf32_rna(v0.x); v0.y = tf32_rna(v0.y);
                v1.x = tf32_rna(v1.x); v1.y = tf32_rna(v1.y);
            }
            *(float2*)(C + (size_t)r * Ntot + col)       = v0;
            *(float2*)(C + (size_t)(r + 8) * Ntot + col) = v1;
        }
}

// ---------------------------------------------------------------------------
// 3-pass split-bf16 HMMA GEMM (unchanged from R5)
//   BT=true : B stored [N][K] (NT);  BT=false: B stored [K][N] (NN, ldsm.trans)
// ---------------------------------------------------------------------------
template <bool BT, bool EPI_SPLIT>
__device__ __forceinline__ void gemm_mma(const bf16* __restrict__ Ahg, const bf16* __restrict__ Alg,
                                         const bf16* __restrict__ Bhg, const bf16* __restrict__ Blg,
                                         float* Cf, bf16* Chi, bf16* Clo,
                                         int Ntot, int K, float scale)
{
    extern __shared__ char smc[];
    const uint32_t sb  = smem_u32(smc);
    const int tid  = threadIdx.x;
    const int lane = tid & 31;
    const int wid  = tid >> 5;
    const int wr   = wid >> 1;
    const int wc   = wid & 1;
    const int m0   = blockIdx.y * 128;
    const int n0   = blockIdx.x * 128;

    float acc[4][8][4];
#pragma unroll
    for (int i = 0; i < 4; i++)
#pragma unroll
        for (int j = 0; j < 8; j++)
#pragma unroll
            for (int e = 0; e < 4; e++) acc[i][j][e] = 0.f;

    const int nch = K / KCH;

    auto stage = [&](int c, int s) {
        const uint32_t base = sb + s * STAGE;
        const int k0 = c * KCH;
#pragma unroll
        for (int i = 0; i < 4; i++) {
            int u = tid + i * 128;
            int row = u >> 2, ch = u & 3;
            uint32_t off = swA((uint32_t)(row * 64 + ch * 16));
            const size_t ga = (size_t)(m0 + row) * K + k0 + ch * 8;
            cpa16(base + S_AH + off, Ahg + ga);
            cpa16(base + S_AL + off, Alg + ga);
        }
        if (BT) {
#pragma unroll
            for (int i = 0; i < 4; i++) {
                int u = tid + i * 128;
                int row = u >> 2, ch = u & 3;
                uint32_t off = swA((uint32_t)(row * 64 + ch * 16));
                const size_t gb = (size_t)(n0 + row) * K + k0 + ch * 8;
                cpa16(base + S_BH + off, Bhg + gb);
                cpa16(base + S_BL + off, Blg + gb);
            }
        } else {
#pragma unroll
            for (int i = 0; i < 4; i++) {
                int u = tid + i * 128;
                int kr = u >> 4, ch = u & 15;
                uint32_t off = swB((uint32_t)(kr * 256 + ch * 16));
                const size_t gb = (size_t)(k0 + kr) * Ntot + n0 + ch * 8;
                cpa16(base + S_BH + off, Bhg + gb);
                cpa16(base + S_BL + off, Blg + gb);
            }
        }
        cpa_commit();
    };

    auto compute = [&](int s) {
        const uint32_t base = sb + s * STAGE;
#pragma unroll
        for (int ks = 0; ks < KCH / 16; ks++) {
            const uint32_t aoff =
                swA((uint32_t)((wr * 64 + (lane & 15)) * 64 + (ks * 2 + (lane >> 4)) * 16));
            uint32_t Ah[4][4], Bh[4][4], Bl[4][4];
#pragma unroll
            for (int mt = 0; mt < 4; mt++)
                ldsm4(base + S_AH + aoff + mt * 1024, Ah[mt]);
            if (BT) {
                const uint32_t boff =
                    swA((uint32_t)((wc * 64 + (lane >> 4) * 8 + (lane & 7)) * 64 +
                                   (ks * 2 + ((lane >> 3) & 1)) * 16));
#pragma unroll
                for (int ng = 0; ng < 4; ng++) {
                    ldsm4(base + S_BH + boff + ng * 1024, Bh[ng]);
                    ldsm4(base + S_BL + boff + ng * 1024, Bl[ng]);
                }
            } else {
#pragma unroll
                for (int ng = 0; ng < 4; ng++) {
                    const uint32_t boff =
                        swB((uint32_t)((ks * 16 + (lane & 15)) * 256 +
                                       wc * 128 + (ng * 2 + (lane >> 4)) * 16));
                    ldsm4t(base + S_BH + boff, Bh[ng]);
                    ldsm4t(base + S_BL + boff, Bl[ng]);
                }
            }
#pragma unroll
            for (int mt = 0; mt < 4; mt++)
#pragma unroll
                for (int ng = 0; ng < 4; ng++) {
                    mma16816(acc[mt][ng * 2],     Ah[mt], Bh[ng][0], Bh[ng][1]);
                    mma16816(acc[mt][ng * 2 + 1], Ah[mt], Bh[ng][2], Bh[ng][3]);
                }
#pragma unroll
            for (int mt = 0; mt < 4; mt++)
#pragma unroll
                for (int ng = 0; ng < 4; ng++) {
                    mma16816(acc[mt][ng * 2],     Ah[mt], Bl[ng][0], Bl[ng][1]);
                    mma16816(acc[mt][ng * 2 + 1], Ah[mt], Bl[ng][2], Bl[ng][3]);
                }
            uint32_t Al[4][4];
#pragma unroll
            for (int mt = 0; mt < 4; mt++)
                ldsm4(base + S_AL + aoff + mt * 1024, Al[mt]);
#pragma unroll
            for (int mt = 0; mt < 4; mt++)
#pragma unroll
                for (int ng = 0; ng < 4; ng++) {
                    mma16816(acc[mt][ng * 2],     Al[mt], Bh[ng][0], Bh[ng][1]);
                    mma16816(acc[mt][ng * 2 + 1], Al[mt], Bh[ng][2], Bh[ng][3]);
                }
        }
    };

    stage(0, 0);
    if (nch > 1) stage(1, 1);
    for (int c = 0; c < nch; c++) {
        cpa_wait1();
        __syncthreads();
        if (c + 2 < nch) stage(c + 2, (c + 2) % NSTAGE);
        compute(c % NSTAGE);
    }

#pragma unroll
    for (int mt = 0; mt < 4; mt++)
#pragma unroll
        for (int nt = 0; nt < 8; nt++) {
            const float* a4 = acc[mt][nt];
            const int r   = m0 + wr * 64 + mt * 16 + (lane >> 2);
            const int col = n0 + wc * 64 + nt * 8 + (lane & 3) * 2;
            if (EPI_SPLIT) {
                uint32_t h, l;
                split2(a4[0] * scale, a4[1] * scale, h, l);
                *(uint32_t*)(Chi + (size_t)r * Ntot + col) = h;
                *(uint32_t*)(Clo + (size_t)r * Ntot + col) = l;
                split2(a4[2] * scale, a4[3] * scale, h, l);
                *(uint32_t*)(Chi + (size_t)(r + 8) * Ntot + col) = h;
                *(uint32_t*)(Clo + (size_t)(r + 8) * Ntot + col) = l;
            } else {
                *(float2*)(Cf + (size_t)r * Ntot + col) =
                    make_float2(a4[0] * scale, a4[1] * scale);
                *(float2*)(Cf + (size_t)(r + 8) * Ntot + col) =
                    make_float2(a4[2] * scale, a4[3] * scale);
            }
        }
}

// ---------------------------------------------------------------------------
// preprocessing
// x -> tf32-rounded fp32 AND bf16 hi/lo
__global__ __launch_bounds__(256) void prep_x_kernel(const float* __restrict__ in, int n4)
{
    int i = blockIdx.x * 256 + threadIdx.x;
    if (i >= n4) return;
    float4 v = ((const float4*)in)[i];
    float4 t;
    t.x = tf32_rna(v.x); t.y = tf32_rna(v.y);
    t.z = tf32_rna(v.z); t.w = tf32_rna(v.w);
    ((float4*)g_x32)[i] = t;
    uint32_t h0, l0, h1, l1;
    split2(v.x, v.y, h0, l0);
    split2(v.z, v.w, h1, l1);
    ((uint2*)g_xh)[i] = make_uint2(h0, h1);
    ((uint2*)g_xl)[i] = make_uint2(l0, l1);
}
// Wq/Wk -> tf32-rounded fp32
__global__ __launch_bounds__(256) void round_w_kernel(const float* __restrict__ in,
                                                      float* __restrict__ out, int n4)
{
    int i = blockIdx.x * 256 + threadIdx.x;
    if (i >= n4) return;
    float4 v = ((const float4*)in)[i];
    v.x = tf32_rna(v.x); v.y = tf32_rna(v.y);
    v.z = tf32_rna(v.z); v.w = tf32_rna(v.w);
    ((float4*)out)[i] = v;
}
// Wv -> bf16 hi/lo
__global__ __launch_bounds__(256) void split_wv_kernel(const float* __restrict__ in, int n4)
{
    int i = blockIdx.x * 256 + threadIdx.x;
    if (i >= n4) return;
    float4 v = ((const float4*)in)[i];
    uint32_t h0, l0, h1, l1;
    split2(v.x, v.y, h0, l0);
    split2(v.z, v.w, h1, l1);
    ((uint2*)g_wvh)[i] = make_uint2(h0, h1);
    ((uint2*)g_wvl)[i] = make_uint2(l0, l1);
}

// ---------------------------------------------------------------------------
__global__ __launch_bounds__(128, 2) void qk_kernel()
{
    const int z = blockIdx.z;                 // 0 -> Q, 1 -> K
    gemm_tf32<true>(g_x32, g_w32 + (size_t)z * DD * DD,
                    z ? g_k32 : g_q32, DD, DD, 1.0f);
}

__global__ __launch_bounds__(128, 2) void v_kernel()
{
    gemm_mma<true, true>(g_xh, g_xl, g_wvh, g_wvl,
                         nullptr, g_vh, g_vl, DD, DD, 1.0f);
}

__global__ __launch_bounds__(128, 2) void scores_kernel()
{
    const int b = blockIdx.z;
    gemm_tf32<false>(g_q32 + (size_t)b * TT * DD,
                     g_k32 + (size_t)b * TT * DD,
                     g_S + (size_t)b * TT * TT,
                     TT, DD, 0.03125f /* 1/sqrt(1024) */);
}

__global__ __launch_bounds__(128, 2) void out_kernel(float* __restrict__ out)
{
    const int b = blockIdx.z;
    gemm_mma<false, false>(g_ph + (size_t)b * TT * TT, g_pl + (size_t)b * TT * TT,
                           g_vh + (size_t)b * TT * DD, g_vl + (size_t)b * TT * DD,
                           out + (size_t)b * TT * DD, nullptr, nullptr,
                           DD, TT, 1.0f);
}

// Row softmax: g_S fp32 -> probabilities as hi/lo bf16 (g_ph, g_pl)
__global__ __launch_bounds__(256) void softmax_kernel()
{
    const size_t row = blockIdx.x;
    const float* r = g_S + row * TT;
    const int t = threadIdx.x;

    float v[8];
#pragma unroll
    for (int i = 0; i < 8; i++) v[i] = r[t + i * 256];

    float m = -CUDART_INF_F;
#pragma unroll
    for (int i = 0; i < 8; i++) m = fmaxf(m, v[i]);

    __shared__ float red[256];
    red[t] = m;
    __syncthreads();
    for (int s = 128; s > 0; s >>= 1) {
        if (t < s) red[t] = fmaxf(red[t], red[t + s]);
        __syncthreads();
    }
    m = red[0];
    __syncthreads();

    float sum = 0.f;
#pragma unroll
    for (int i = 0; i < 8; i++) { v[i] = __expf(v[i] - m); sum += v[i]; }
    red[t] = sum;
    __syncthreads();
    for (int s = 128; s > 0; s >>= 1) {
        if (t < s) red[t] += red[t + s];
        __syncthreads();
    }
    const float inv = 1.0f / red[0];

    bf16* ph = g_ph + row * TT;
    bf16* pl = g_pl + row * TT;
#pragma unroll
    for (int i = 0; i < 8; i++) {
        float p = v[i] * inv;
        __nv_bfloat16 h = __float2bfloat16_rn(p);
        __nv_bfloat16 l = __float2bfloat16_rn(p - __bfloat162float(h));
        ph[t + i * 256] = h;
        pl[t + i * 256] = l;
    }
}

extern "C" void kernel_launch(void* const* d_in, const int* in_sizes, int n_in,
                              void* d_out, int out_size)
{
    (void)in_sizes; (void)n_in; (void)out_size;
    const float* x  = (const float*)d_in[0];
    const float* Wq = (const float*)d_in[1];
    const float* Wk = (const float*)d_in[2];
    const float* Wv = (const float*)d_in[3];
    float* out = (float*)d_out;

    cudaFuncSetAttribute(qk_kernel,     cudaFuncAttributeMaxDynamicSharedMemorySize, SMEM_BYTES);
    cudaFuncSetAttribute(v_kernel,      cudaFuncAttributeMaxDynamicSharedMemorySize, SMEM_BYTES);
    cudaFuncSetAttribute(scores_kernel, cudaFuncAttributeMaxDynamicSharedMemorySize, SMEM_BYTES);
    cudaFuncSetAttribute(out_kernel,    cudaFuncAttributeMaxDynamicSharedMemorySize, SMEM_BYTES);

    float* w32;
    cudaGetSymbolAddress((void**)&w32, g_w32);

    const int nx4 = BB * TT * DD / 4;
    const int nw4 = DD * DD / 4;
    prep_x_kernel<<<(nx4 + 255) / 256, 256>>>(x, nx4);
    round_w_kernel<<<(nw4 + 255) / 256, 256>>>(Wq, w32, nw4);
    round_w_kernel<<<(nw4 + 255) / 256, 256>>>(Wk, w32 + (size_t)DD * DD, nw4);
    split_wv_kernel<<<(nw4 + 255) / 256, 256>>>(Wv, nw4);

    dim3 gQK(DD / 128, (BB * TT) / 128, 2);    // (8, 64, 2) tf32
    qk_kernel<<<gQK, 128, SMEM_BYTES>>>();

    dim3 gV(DD / 128, (BB * TT) / 128);        // (8, 64) bf16 3-pass
    v_kernel<<<gV, 128, SMEM_BYTES>>>();

    dim3 gS(TT / 128, TT / 128, BB);           // (16, 16, 4) tf32
    scores_kernel<<<gS, 128, SMEM_BYTES>>>();

    softmax_kernel<<<BB * TT, 256>>>();

    dim3 gO(DD / 128, TT / 128, BB);           // (8, 16, 4) bf16 3-pass
    out_kernel<<<gO, 128, SMEM_BYTES>>>(out);
}

// round 7
// speedup vs baseline: 4.8260x; 1.1920x over previous
#include <cuda_runtime.h>
#include <stdint.h>
#include <math_constants.h>

#define BB 4
#define TT 2048
#define DD 1024
#define KCH 32

// ---- scratch (allocation-free rule: __device__ globals) ----
__device__ __align__(256) float g_x32[(size_t)BB * TT * DD];   // tf32-rounded x
__device__ __align__(256) float g_w32[3 * (size_t)DD * DD];    // tf32-rounded Wq,Wk,Wv
__device__ __align__(256) float g_q32[(size_t)BB * TT * DD];
__device__ __align__(256) float g_k32[(size_t)BB * TT * DD];
__device__ __align__(256) float g_v32[(size_t)BB * TT * DD];
__device__ __align__(256) float g_S[(size_t)BB * TT * TT];     // scores, then P (in-place)

// SMEM: 3 stages x (A 16K | B 16K)
#define STAGE 32768
#define NSTAGE 3
#define SMEM_BYTES (NSTAGE * STAGE)   // 98304

__device__ __forceinline__ uint32_t smem_u32(const void* p) {
    uint32_t a;
    asm("{ .reg .u64 t; cvta.to.shared.u64 t, %1; cvt.u32.u64 %0, t; }" : "=r"(a) : "l"(p));
    return a;
}
__device__ __forceinline__ void cpa16(uint32_t dst, const void* src) {
    asm volatile("cp.async.cg.shared.global [%0], [%1], 16;" :: "r"(dst), "l"(src));
}
__device__ __forceinline__ void cpa_commit() { asm volatile("cp.async.commit_group;" ::: "memory"); }
__device__ __forceinline__ void cpa_wait1()  { asm volatile("cp.async.wait_group 1;" ::: "memory"); }

__device__ __forceinline__ void mma_tf32(float c[4], const uint32_t a[4],
                                         uint32_t b0, uint32_t b1) {
    asm volatile("mma.sync.aligned.m16n8k8.row.col.f32.tf32.tf32.f32 "
                 "{%0,%1,%2,%3}, {%4,%5,%6,%7}, {%8,%9}, {%0,%1,%2,%3};"
                 : "+f"(c[0]), "+f"(c[1]), "+f"(c[2]), "+f"(c[3])
                 : "r"(a[0]), "r"(a[1]), "r"(a[2]), "r"(a[3]), "r"(b0), "r"(b1));
}
__device__ __forceinline__ uint32_t lds32(uint32_t addr) {
    uint32_t v;
    asm volatile("ld.shared.b32 %0, [%1];" : "=r"(v) : "r"(addr));
    return v;
}
__device__ __forceinline__ float tf32_rna(float v) {
    uint32_t o;
    asm("cvt.rna.tf32.f32 %0, %1;" : "=r"(o) : "f"(v));
    return __uint_as_float(o);
}

// ---------------------------------------------------------------------------
// 1xTF32 GEMM: C[m,n] = scale * sum_k A[m,k] * B'[k,n], operands tf32-rounded.
//   BT=true : B stored [N][K] (NT)  — sw128 rows, fragment rows via LDS.32
//   BT=false: B stored [K][N] (NN) — [32k][512B] tile, per-k XOR-bank swizzle
// 128x128 CTA, 4 warps (2x2 -> 64x64 warp tile), KCH=32, 3-stage cp.async.
// ---------------------------------------------------------------------------
template <bool BT, bool ROUND_OUT>
__device__ __forceinline__ void gemm_tf32(const float* __restrict__ A,
                                          const float* __restrict__ Bm,
                                          float* __restrict__ C,
                                          int Ntot, int K, float scale)
{
    extern __shared__ char smc[];
    const uint32_t sb  = smem_u32(smc);
    const int tid  = threadIdx.x;
    const int lane = tid & 31;
    const int wid  = tid >> 5;
    const int wr   = wid >> 1;
    const int wc   = wid & 1;
    const int m0   = blockIdx.y * 128;
    const int n0   = blockIdx.x * 128;

    float acc[4][8][4];
#pragma unroll
    for (int i = 0; i < 4; i++)
#pragma unroll
        for (int j = 0; j < 8; j++)
#pragma unroll
            for (int e = 0; e < 4; e++) acc[i][j][e] = 0.f;

    const int nch = K / KCH;

    auto stage = [&](int c, int s) {
        const uint32_t base = sb + s * STAGE;
        const int k0 = c * KCH;
        // A tile: [128 rows][32 floats] = 128B rows, sw128 (8 chunks/row)
#pragma unroll
        for (int i = 0; i < 8; i++) {
            int u = tid + i * 128;
            int row = u >> 3, ch = u & 7;
            uint32_t off = (uint32_t)(row * 128 + ((ch * 16) ^ ((row & 7) * 16)));
            cpa16(base + off, A + (size_t)(m0 + row) * K + k0 + ch * 4);
        }
        if (BT) {
            // B tile: [128 n-rows][32 floats], same layout as A
#pragma unroll
            for (int i = 0; i < 8; i++) {
                int u = tid + i * 128;
                int row = u >> 3, ch = u & 7;
                uint32_t off = (uint32_t)(row * 128 + ((ch * 16) ^ ((row & 7) * 16)));
                cpa16(base + 16384 + off, Bm + (size_t)(n0 + row) * K + k0 + ch * 4);
            }
        } else {
            // B tile: [32 k-rows][128 n floats] = 512B rows; XOR bits 5-6 per k
#pragma unroll
            for (int i = 0; i < 8; i++) {
                int u = tid + i * 128;
                int kr = u >> 5, ch = u & 31;
                uint32_t off = (uint32_t)(kr * 512 + ((ch * 16) ^ ((kr & 3) << 5)));
                cpa16(base + 16384 + off, Bm + (size_t)(k0 + kr) * Ntot + n0 + ch * 4);
            }
        }
        cpa_commit();
    };

    const int ar  = lane >> 2;                  // 0..7
    const int ac4 = (lane & 3) * 4;             // k-element byte offset in k8
    const uint32_t xr = (uint32_t)(ar * 16);    // sw128 XOR (lane constant)
    uint32_t rA[4];
#pragma unroll
    for (int mt = 0; mt < 4; mt++) rA[mt] = (uint32_t)((wr * 64 + mt * 16 + ar) * 128);

    // NT B fragment rows
    uint32_t rB[8];
#pragma unroll
    for (int nt = 0; nt < 8; nt++) rB[nt] = (uint32_t)((wc * 64 + nt * 8 + ar) * 128);
    // NN B fragment addressing
    const uint32_t kb  = (uint32_t)((lane & 3) * 512);       // k-row byte base
    const uint32_t xk  = (uint32_t)((lane & 3) << 5);        // bank XOR (lane constant)
    uint32_t nb[8];
#pragma unroll
    for (int nt = 0; nt < 8; nt++)
        nb[nt] = ((uint32_t)((wc * 64 + nt * 8 + ar) * 4)) ^ xk;

    auto compute = [&](int s) {
        const uint32_t base  = sb + s * STAGE;
        const uint32_t baseB = base + 16384;
#pragma unroll
        for (int ks = 0; ks < 4; ks++) {                 // k8 slices of KCH=32
            const uint32_t c0 = (uint32_t)(ks * 32 + ac4);
            const uint32_t o0 = c0 ^ xr, o1 = (c0 + 16) ^ xr;
            uint32_t a[4][4];
#pragma unroll
            for (int mt = 0; mt < 4; mt++) {
                a[mt][0] = lds32(base + rA[mt] + o0);
                a[mt][1] = lds32(base + rA[mt] + 1024 + o0);   // row+8
                a[mt][2] = lds32(base + rA[mt] + o1);
                a[mt][3] = lds32(base + rA[mt] + 1024 + o1);
            }
#pragma unroll
            for (int nt = 0; nt < 8; nt++) {
                uint32_t b0, b1;
                if (BT) {
                    b0 = lds32(baseB + rB[nt] + o0);
                    b1 = lds32(baseB + rB[nt] + o1);
                } else {
                    const uint32_t ad = baseB + (uint32_t)(ks * 4096) + kb + nb[nt];
                    b0 = lds32(ad);
                    b1 = lds32(ad + 2048);                     // k+4 rows
                }
#pragma unroll
                for (int mt = 0; mt < 4; mt++)
                    mma_tf32(acc[mt][nt], a[mt], b0, b1);
            }
        }
    };

    stage(0, 0);
    if (nch > 1) stage(1, 1);
    for (int c = 0; c < nch; c++) {
        cpa_wait1();
        __syncthreads();
        if (c + 2 < nch) stage(c + 2, (c + 2) % NSTAGE);
        compute(c % NSTAGE);
    }

#pragma unroll
    for (int mt = 0; mt < 4; mt++)
#pragma unroll
        for (int nt = 0; nt < 8; nt++) {
            const float* a4 = acc[mt][nt];
            const int r   = m0 + wr * 64 + mt * 16 + (lane >> 2);
            const int col = n0 + wc * 64 + nt * 8 + (lane & 3) * 2;
            float2 v0 = make_float2(a4[0] * scale, a4[1] * scale);
            float2 v1 = make_float2(a4[2] * scale, a4[3] * scale);
            if (ROUND_OUT) {
                v0.x = tf32_rna(v0.x); v0.y = tf32_rna(v0.y);
                v1.x = tf32_rna(v1.x); v1.y = tf32_rna(v1.y);
            }
            *(float2*)(C + (size_t)r * Ntot + col)       = v0;
            *(float2*)(C + (size_t)(r + 8) * Ntot + col) = v1;
        }
}

// ---------------------------------------------------------------------------
// preprocessing: fp32 -> tf32-rounded fp32
__global__ __launch_bounds__(256) void round_kernel(const float* __restrict__ in,
                                                    float* __restrict__ out, int n4)
{
    int i = blockIdx.x * 256 + threadIdx.x;
    if (i >= n4) return;
    float4 v = ((const float4*)in)[i];
    v.x = tf32_rna(v.x); v.y = tf32_rna(v.y);
    v.z = tf32_rna(v.z); v.w = tf32_rna(v.w);
    ((float4*)out)[i] = v;
}

// ---------------------------------------------------------------------------
__global__ __launch_bounds__(128, 2) void qkv_kernel()
{
    const int z = blockIdx.z;                 // 0->Q, 1->K, 2->V
    float* C = (z == 0) ? g_q32 : (z == 1) ? g_k32 : g_v32;
    gemm_tf32<true, true>(g_x32, g_w32 + (size_t)z * DD * DD, C, DD, DD, 1.0f);
}

__global__ __launch_bounds__(128, 2) void scores_kernel()
{
    const int b = blockIdx.z;
    gemm_tf32<true, false>(g_q32 + (size_t)b * TT * DD,
                           g_k32 + (size_t)b * TT * DD,
                           g_S + (size_t)b * TT * TT,
                           TT, DD, 0.03125f /* 1/sqrt(1024) */);
}

__global__ __launch_bounds__(128, 2) void out_kernel(float* __restrict__ out)
{
    const int b = blockIdx.z;
    gemm_tf32<false, false>(g_S + (size_t)b * TT * TT,
                            g_v32 + (size_t)b * TT * DD,
                            out + (size_t)b * TT * DD,
                            DD, TT, 1.0f);
}

// Row softmax over g_S (8192 rows of 2048), in-place, output tf32-rounded P.
__global__ __launch_bounds__(256) void softmax_kernel()
{
    const size_t row = blockIdx.x;
    float* r = g_S + row * TT;
    const int t = threadIdx.x;

    float v[8];
#pragma unroll
    for (int i = 0; i < 8; i++) v[i] = r[t + i * 256];

    float m = -CUDART_INF_F;
#pragma unroll
    for (int i = 0; i < 8; i++) m = fmaxf(m, v[i]);

    __shared__ float red[256];
    red[t] = m;
    __syncthreads();
    for (int s = 128; s > 0; s >>= 1) {
        if (t < s) red[t] = fmaxf(red[t], red[t + s]);
        __syncthreads();
    }
    m = red[0];
    __syncthreads();

    float sum = 0.f;
#pragma unroll
    for (int i = 0; i < 8; i++) { v[i] = __expf(v[i] - m); sum += v[i]; }
    red[t] = sum;
    __syncthreads();
    for (int s = 128; s > 0; s >>= 1) {
        if (t < s) red[t] += red[t + s];
        __syncthreads();
    }
    const float inv = 1.0f / red[0];
#pragma unroll
    for (int i = 0; i < 8; i++) r[t + i * 256] = tf32_rna(v[i] * inv);
}

extern "C" void kernel_launch(void* const* d_in, const int* in_sizes, int n_in,
                              void* d_out, int out_size)
{
    (void)in_sizes; (void)n_in; (void)out_size;
    const float* x  = (const float*)d_in[0];
    const float* Wq = (const float*)d_in[1];
    const float* Wk = (const float*)d_in[2];
    const float* Wv = (const float*)d_in[3];
    float* out = (float*)d_out;

    cudaFuncSetAttribute(qkv_kernel,    cudaFuncAttributeMaxDynamicSharedMemorySize, SMEM_BYTES);
    cudaFuncSetAttribute(scores_kernel, cudaFuncAttributeMaxDynamicSharedMemorySize, SMEM_BYTES);
    cudaFuncSetAttribute(out_kernel,    cudaFuncAttributeMaxDynamicSharedMemorySize, SMEM_BYTES);

    float *x32, *w32;
    cudaGetSymbolAddress((void**)&x32, g_x32);
    cudaGetSymbolAddress((void**)&w32, g_w32);

    const int nx4 = BB * TT * DD / 4;
    const int nw4 = DD * DD / 4;
    round_kernel<<<(nx4 + 255) / 256, 256>>>(x, x32, nx4);
    round_kernel<<<(nw4 + 255) / 256, 256>>>(Wq, w32, nw4);
    round_kernel<<<(nw4 + 255) / 256, 256>>>(Wk, w32 + (size_t)DD * DD, nw4);
    round_kernel<<<(nw4 + 255) / 256, 256>>>(Wv, w32 + 2 * (size_t)DD * DD, nw4);

    dim3 gQKV(DD / 128, (BB * TT) / 128, 3);   // (8, 64, 3)
    qkv_kernel<<<gQKV, 128, SMEM_BYTES>>>();

    dim3 gS(TT / 128, TT / 128, BB);           // (16, 16, 4)
    scores_kernel<<<gS, 128, SMEM_BYTES>>>();

    softmax_kernel<<<BB * TT, 256>>>();

    dim3 gO(DD / 128, TT / 128, BB);           // (8, 16, 4)
    out_kernel<<<gO, 128, SMEM_BYTES>>>(out);
}

// round 8
// speedup vs baseline: 8.7879x; 1.8210x over previous
#include <cuda_runtime.h>
#include <cuda_fp16.h>
#include <stdint.h>
#include <math_constants.h>

#define BB 4
#define TT 2048
#define DD 1024
#define KCH 64

// ---- scratch (allocation-free rule: __device__ globals) ----
__device__ __align__(256) __half g_x16[(size_t)BB * TT * DD];
__device__ __align__(256) __half g_w16[3 * (size_t)DD * DD];     // Wq,Wk,Wv
__device__ __align__(256) __half g_q16[(size_t)BB * TT * DD];
__device__ __align__(256) __half g_k16[(size_t)BB * TT * DD];
__device__ __align__(256) __half g_v16[(size_t)BB * TT * DD];
__device__ __align__(256) float  g_S[(size_t)BB * TT * TT];      // fp32 scores
__device__ __align__(256) __half g_p16[(size_t)BB * TT * TT];    // fp16 probs

// SMEM: 3 stages x (A 16K | B 16K)
#define STAGE 32768
#define NSTAGE 3
#define SMEM_BYTES (NSTAGE * STAGE)   // 98304

__device__ __forceinline__ uint32_t smem_u32(const void* p) {
    uint32_t a;
    asm("{ .reg .u64 t; cvta.to.shared.u64 t, %1; cvt.u32.u64 %0, t; }" : "=r"(a) : "l"(p));
    return a;
}
__device__ __forceinline__ void cpa16(uint32_t dst, const void* src) {
    asm volatile("cp.async.cg.shared.global [%0], [%1], 16;" :: "r"(dst), "l"(src));
}
__device__ __forceinline__ void cpa_commit() { asm volatile("cp.async.commit_group;" ::: "memory"); }
__device__ __forceinline__ void cpa_wait1()  { asm volatile("cp.async.wait_group 1;" ::: "memory"); }

__device__ __forceinline__ void ldsm4(uint32_t addr, uint32_t r[4]) {
    asm volatile("ldmatrix.sync.aligned.m8n8.x4.shared.b16 {%0,%1,%2,%3}, [%4];"
                 : "=r"(r[0]), "=r"(r[1]), "=r"(r[2]), "=r"(r[3]) : "r"(addr));
}
__device__ __forceinline__ void ldsm4t(uint32_t addr, uint32_t r[4]) {
    asm volatile("ldmatrix.sync.aligned.m8n8.x4.trans.shared.b16 {%0,%1,%2,%3}, [%4];"
                 : "=r"(r[0]), "=r"(r[1]), "=r"(r[2]), "=r"(r[3]) : "r"(addr));
}
__device__ __forceinline__ void mma_f16(float c[4], const uint32_t a[4],
                                        uint32_t b0, uint32_t b1) {
    asm volatile("mma.sync.aligned.m16n8k16.row.col.f32.f16.f16.f32 "
                 "{%0,%1,%2,%3}, {%4,%5,%6,%7}, {%8,%9}, {%0,%1,%2,%3};"
                 : "+f"(c[0]), "+f"(c[1]), "+f"(c[2]), "+f"(c[3])
                 : "r"(a[0]), "r"(a[1]), "r"(a[2]), "r"(a[3]), "r"(b0), "r"(b1));
}

// ---------------------------------------------------------------------------
// 1-pass fp16 HMMA GEMM: C[m,n] = scale * sum_k A[m,k] * B'[k,n]
//   BT=true : B stored [N][K] (NT, ldsm4)
//   BT=false: B stored [K][N] (NN, ldsm4t on 256B-row tile)
//   EPI_HALF: write fp16 C, else fp32 C
// 128x128 CTA tile, 4 warps (2x2 -> 64x64 warp tile), K-chunk 64,
// 3-stage cp.async pipeline.
// ---------------------------------------------------------------------------
template <bool BT, bool EPI_HALF>
__device__ __forceinline__ void gemm_f16(const __half* __restrict__ A,
                                         const __half* __restrict__ Bm,
                                         float* Cf, __half* Ch,
                                         int Ntot, int K, float scale)
{
    extern __shared__ char smc[];
    const uint32_t sb  = smem_u32(smc);
    const int tid  = threadIdx.x;
    const int lane = tid & 31;
    const int wid  = tid >> 5;
    const int wr   = wid >> 1;
    const int wc   = wid & 1;
    const int m0   = blockIdx.y * 128;
    const int n0   = blockIdx.x * 128;

    float acc[4][8][4];
#pragma unroll
    for (int i = 0; i < 4; i++)
#pragma unroll
        for (int j = 0; j < 8; j++)
#pragma unroll
            for (int e = 0; e < 4; e++) acc[i][j][e] = 0.f;

    const int nch = K / KCH;

    auto stage = [&](int c, int s) {
        const uint32_t base = sb + s * STAGE;
        const int k0 = c * KCH;
        // A tile: [128 rows][64 fp16] = 128B rows; chunk-XOR (row&7)
#pragma unroll
        for (int i = 0; i < 8; i++) {
            int u = tid + i * 128;
            int row = u >> 3, ch = u & 7;
            uint32_t off = (uint32_t)(row * 128 + ((ch * 16) ^ ((row & 7) * 16)));
            cpa16(base + off, A + (size_t)(m0 + row) * K + k0 + ch * 8);
        }
        if (BT) {
#pragma unroll
            for (int i = 0; i < 8; i++) {
                int u = tid + i * 128;
                int row = u >> 3, ch = u & 7;
                uint32_t off = (uint32_t)(row * 128 + ((ch * 16) ^ ((row & 7) * 16)));
                cpa16(base + 16384 + off, Bm + (size_t)(n0 + row) * K + k0 + ch * 8);
            }
        } else {
            // B tile: [64 k-rows][128 n fp16] = 256B rows; chunk-XOR (k&7)
#pragma unroll
            for (int i = 0; i < 8; i++) {
                int u = tid + i * 128;
                int kr = u >> 4, ch = u & 15;
                uint32_t off = (uint32_t)(kr * 256 + ((ch * 16) ^ ((kr & 7) * 16)));
                cpa16(base + 16384 + off, Bm + (size_t)(k0 + kr) * Ntot + n0 + ch * 8);
            }
        }
        cpa_commit();
    };

    auto compute = [&](int s) {
        const uint32_t base = sb + s * STAGE;
#pragma unroll
        for (int ks = 0; ks < KCH / 16; ks++) {
            // A fragment: 16 rows x k16
            const int arow = lane & 15;
            const uint32_t ach = (uint32_t)(((ks * 2 + (lane >> 4)) * 16) ^ ((lane & 7) * 16));
            uint32_t Af[4][4], Bf[4][4];
#pragma unroll
            for (int mt = 0; mt < 4; mt++) {
                const uint32_t aoff =
                    (uint32_t)((wr * 64 + mt * 16 + arow) * 128) + ach;
                ldsm4(base + aoff, Af[mt]);
            }
            if (BT) {
                const int brow = (lane >> 4) * 8 + (lane & 7);
                const uint32_t bch =
                    (uint32_t)(((ks * 2 + ((lane >> 3) & 1)) * 16) ^ ((lane & 7) * 16));
#pragma unroll
                for (int ng = 0; ng < 4; ng++) {
                    const uint32_t boff =
                        (uint32_t)((wc * 64 + ng * 16 + brow) * 128) + bch;
                    ldsm4(base + 16384 + boff, Bf[ng]);
                }
            } else {
                const int krow = ks * 16 + (lane & 15);
#pragma unroll
                for (int ng = 0; ng < 4; ng++) {
                    const uint32_t chunk =
                        (uint32_t)(wc * 8 + ng * 2 + (lane >> 4)) ^ (uint32_t)(lane & 7);
                    const uint32_t boff = (uint32_t)(krow * 256) + chunk * 16;
                    ldsm4t(base + 16384 + boff, Bf[ng]);
                }
            }
#pragma unroll
            for (int mt = 0; mt < 4; mt++)
#pragma unroll
                for (int ng = 0; ng < 4; ng++) {
                    mma_f16(acc[mt][ng * 2],     Af[mt], Bf[ng][0], Bf[ng][1]);
                    mma_f16(acc[mt][ng * 2 + 1], Af[mt], Bf[ng][2], Bf[ng][3]);
                }
        }
    };

    stage(0, 0);
    if (nch > 1) stage(1, 1);
    for (int c = 0; c < nch; c++) {
        cpa_wait1();
        __syncthreads();
        if (c + 2 < nch) stage(c + 2, (c + 2) % NSTAGE);
        compute(c % NSTAGE);
    }

    // ---- epilogue ----
#pragma unroll
    for (int mt = 0; mt < 4; mt++)
#pragma unroll
        for (int nt = 0; nt < 8; nt++) {
            const float* a4 = acc[mt][nt];
            const int r   = m0 + wr * 64 + mt * 16 + (lane >> 2);
            const int col = n0 + wc * 64 + nt * 8 + (lane & 3) * 2;
            if (EPI_HALF) {
                __half2 h0 = __floats2half2_rn(a4[0] * scale, a4[1] * scale);
                __half2 h1 = __floats2half2_rn(a4[2] * scale, a4[3] * scale);
                *(__half2*)(Ch + (size_t)r * Ntot + col)       = h0;
                *(__half2*)(Ch + (size_t)(r + 8) * Ntot + col) = h1;
            } else {
                *(float2*)(Cf + (size_t)r * Ntot + col) =
                    make_float2(a4[0] * scale, a4[1] * scale);
                *(float2*)(Cf + (size_t)(r + 8) * Ntot + col) =
                    make_float2(a4[2] * scale, a4[3] * scale);
            }
        }
}

// ---------------------------------------------------------------------------
// preprocessing: fp32 -> fp16
__global__ __launch_bounds__(256) void tohalf_kernel(const float* __restrict__ in,
                                                     __half* __restrict__ out, int n4)
{
    int i = blockIdx.x * 256 + threadIdx.x;
    if (i >= n4) return;
    float4 v = ((const float4*)in)[i];
    __half2 h0 = __floats2half2_rn(v.x, v.y);
    __half2 h1 = __floats2half2_rn(v.z, v.w);
    uint2 o;
    o.x = *reinterpret_cast<uint32_t*>(&h0);
    o.y = *reinterpret_cast<uint32_t*>(&h1);
    ((uint2*)out)[i] = o;
}

// ---------------------------------------------------------------------------
__global__ __launch_bounds__(128, 2) void qkv_kernel()
{
    const int z = blockIdx.z;                 // 0->Q, 1->K, 2->V
    __half* C = (z == 0) ? g_q16 : (z == 1) ? g_k16 : g_v16;
    gemm_f16<true, true>(g_x16, g_w16 + (size_t)z * DD * DD, nullptr, C, DD, DD, 1.0f);
}

__global__ __launch_bounds__(128, 2) void scores_kernel()
{
    const int b = blockIdx.z;
    gemm_f16<true, false>(g_q16 + (size_t)b * TT * DD,
                          g_k16 + (size_t)b * TT * DD,
                          g_S + (size_t)b * TT * TT, nullptr,
                          TT, DD, 0.03125f /* 1/sqrt(1024) */);
}

__global__ __launch_bounds__(128, 2) void out_kernel(float* __restrict__ out)
{
    const int b = blockIdx.z;
    gemm_f16<false, false>(g_p16 + (size_t)b * TT * TT,
                           g_v16 + (size_t)b * TT * DD,
                           out + (size_t)b * TT * DD, nullptr,
                           DD, TT, 1.0f);
}

// Row softmax: g_S fp32 -> g_p16 fp16 probabilities
__global__ __launch_bounds__(256) void softmax_kernel()
{
    const size_t row = blockIdx.x;
    const float* r = g_S + row * TT;
    const int t = threadIdx.x;

    float v[8];
#pragma unroll
    for (int i = 0; i < 8; i++) v[i] = r[t + i * 256];

    float m = -CUDART_INF_F;
#pragma unroll
    for (int i = 0; i < 8; i++) m = fmaxf(m, v[i]);

    __shared__ float red[256];
    red[t] = m;
    __syncthreads();
    for (int s = 128; s > 0; s >>= 1) {
        if (t < s) red[t] = fmaxf(red[t], red[t + s]);
        __syncthreads();
    }
    m = red[0];
    __syncthreads();

    float sum = 0.f;
#pragma unroll
    for (int i = 0; i < 8; i++) { v[i] = __expf(v[i] - m); sum += v[i]; }
    red[t] = sum;
    __syncthreads();
    for (int s = 128; s > 0; s >>= 1) {
        if (t < s) red[t] += red[t + s];
        __syncthreads();
    }
    const float inv = 1.0f / red[0];

    __half* p = g_p16 + row * TT;
#pragma unroll
    for (int i = 0; i < 8; i++)
        p[t + i * 256] = __float2half_rn(v[i] * inv);
}

extern "C" void kernel_launch(void* const* d_in, const int* in_sizes, int n_in,
                              void* d_out, int out_size)
{
    (void)in_sizes; (void)n_in; (void)out_size;
    const float* x  = (const float*)d_in[0];
    const float* Wq = (const float*)d_in[1];
    const float* Wk = (const float*)d_in[2];
    const float* Wv = (const float*)d_in[3];
    float* out = (float*)d_out;

    cudaFuncSetAttribute(qkv_kernel,    cudaFuncAttributeMaxDynamicSharedMemorySize, SMEM_BYTES);
    cudaFuncSetAttribute(scores_kernel, cudaFuncAttributeMaxDynamicSharedMemorySize, SMEM_BYTES);
    cudaFuncSetAttribute(out_kernel,    cudaFuncAttributeMaxDynamicSharedMemorySize, SMEM_BYTES);

    __half *x16, *w16;
    cudaGetSymbolAddress((void**)&x16, g_x16);
    cudaGetSymbolAddress((void**)&w16, g_w16);

    const int nx4 = BB * TT * DD / 4;
    const int nw4 = DD * DD / 4;
    tohalf_kernel<<<(nx4 + 255) / 256, 256>>>(x, x16, nx4);
    tohalf_kernel<<<(nw4 + 255) / 256, 256>>>(Wq, w16, nw4);
    tohalf_kernel<<<(nw4 + 255) / 256, 256>>>(Wk, w16 + (size_t)DD * DD, nw4);
    tohalf_kernel<<<(nw4 + 255) / 256, 256>>>(Wv, w16 + 2 * (size_t)DD * DD, nw4);

    dim3 gQKV(DD / 128, (BB * TT) / 128, 3);   // (8, 64, 3)
    qkv_kernel<<<gQKV, 128, SMEM_BYTES>>>();

    dim3 gS(TT / 128, TT / 128, BB);           // (16, 16, 4)
    scores_kernel<<<gS, 128, SMEM_BYTES>>>();

    softmax_kernel<<<BB * TT, 256>>>();

    dim3 gO(DD / 128, TT / 128, BB);           // (8, 16, 4)
    out_kernel<<<gO, 128, SMEM_BYTES>>>(out);
}